// round 3
// baseline (speedup 1.0000x reference)
#include <cuda_runtime.h>
#include <cstdint>

#define N_NODES 100000
#define N_EDGES_MAX 3200000
#define IN_C 64
#define HID_C 64
#define OUT_C 32

// Scratch (static __device__ arrays per harness rules)
__device__ __align__(16) float g_sum1[(size_t)N_NODES * HID_C];   // mean-agg layer1
__device__ __align__(16) float g_h   [(size_t)N_NODES * HID_C];
__device__ __align__(16) float g_p2  [(size_t)N_NODES * OUT_C];
__device__ __align__(16) float g_sum2[(size_t)N_NODES * OUT_C];   // mean-agg layer2
__device__ __align__(16) int   g_eidx[(size_t)2 * N_EDGES_MAX];
__device__ __align__(16) int   g_csr [N_EDGES_MAX];
__device__ __align__(16) int   g_degi[N_NODES];
__device__ __align__(16) int   g_rowstart[N_NODES + 1];
__device__ __align__(16) int   g_cursor[N_NODES];
__device__ int g_is64;

// ---------------------------------------------------------------------------
// Detect int64 vs int32 edge buffer (int64 values < 2^31 -> odd words all 0)
// ---------------------------------------------------------------------------
__global__ void detect_dtype_kernel(const int* __restrict__ ei32) {
    __shared__ int nz;
    if (threadIdx.x == 0) nz = 0;
    __syncthreads();
    int any = 0;
    for (int i = threadIdx.x; i < 8192; i += blockDim.x)
        if (ei32[2 * i + 1] != 0) any = 1;
    if (any) atomicOr(&nz, 1);
    __syncthreads();
    if (threadIdx.x == 0) g_is64 = (nz == 0) ? 1 : 0;
}

// ---------------------------------------------------------------------------
// Convert edges to int32 AND histogram destination degrees (fused).
// ---------------------------------------------------------------------------
__global__ void convert_hist_kernel(const void* __restrict__ ei, int E) {
    int i = blockIdx.x * blockDim.x + threadIdx.x;
    if (i >= 2 * E) return;
    int v;
    if (g_is64) v = (int)((const long long*)ei)[i];
    else        v = ((const int*)ei)[i];
    g_eidx[i] = v;
    if (i >= E) atomicAdd(&g_degi[v], 1);
}

// ---------------------------------------------------------------------------
// Single-block exclusive scan of degrees -> rowstart / cursor.
// ---------------------------------------------------------------------------
__global__ __launch_bounds__(1024) void scan_kernel() {
    __shared__ int ssum[1024];
    int t = threadIdx.x;
    const int CH = (N_NODES + 1023) / 1024;   // 98
    int start = t * CH;
    int endi  = min(start + CH, N_NODES);
    int local = 0;
    for (int i = start; i < endi; i++) local += g_degi[i];
    ssum[t] = local;
    __syncthreads();
    for (int off = 1; off < 1024; off <<= 1) {
        int v = (t >= off) ? ssum[t - off] : 0;
        __syncthreads();
        ssum[t] += v;
        __syncthreads();
    }
    int prefix = (t == 0) ? 0 : ssum[t - 1];
    for (int i = start; i < endi; i++) {
        g_rowstart[i] = prefix;
        g_cursor[i]   = prefix;
        prefix += g_degi[i];
    }
    if (t == 1023) g_rowstart[N_NODES] = ssum[1023];
}

// ---------------------------------------------------------------------------
// Fill CSR: bucket src indices by dst.
// ---------------------------------------------------------------------------
__global__ void fill_kernel(int E) {
    int e = blockIdx.x * blockDim.x + threadIdx.x;
    if (e >= E) return;
    int s = g_eidx[e];
    int d = g_eidx[(size_t)E + e];
    int pos = atomicAdd(&g_cursor[d], 1);
    g_csr[pos] = s;
}

// ---------------------------------------------------------------------------
// agg1: one warp per dst node. mean of x[src] (64 floats; lane = float2).
// ---------------------------------------------------------------------------
__global__ __launch_bounds__(256) void agg1_kernel(const float* __restrict__ x) {
    int warp = (blockIdx.x * blockDim.x + threadIdx.x) >> 5;
    if (warp >= N_NODES) return;
    int lane = threadIdx.x & 31;
    int row = g_rowstart[warp];
    int end = g_rowstart[warp + 1];
    float ax = 0.f, ay = 0.f;
    const float2* x2 = (const float2*)x;
    for (int base = row; base < end; base += 32) {
        int n = end - base;
        int m = min(n, 32);
        int idx = (lane < m) ? g_csr[base + lane] : 0;
        int k = 0;
        for (; k + 4 <= m; k += 4) {
            int s0 = __shfl_sync(0xffffffffu, idx, k);
            int s1 = __shfl_sync(0xffffffffu, idx, k + 1);
            int s2 = __shfl_sync(0xffffffffu, idx, k + 2);
            int s3 = __shfl_sync(0xffffffffu, idx, k + 3);
            float2 v0 = x2[(size_t)s0 * 32 + lane];
            float2 v1 = x2[(size_t)s1 * 32 + lane];
            float2 v2 = x2[(size_t)s2 * 32 + lane];
            float2 v3 = x2[(size_t)s3 * 32 + lane];
            ax += (v0.x + v1.x) + (v2.x + v3.x);
            ay += (v0.y + v1.y) + (v2.y + v3.y);
        }
        for (; k < m; k++) {
            int s = __shfl_sync(0xffffffffu, idx, k);
            float2 v = x2[(size_t)s * 32 + lane];
            ax += v.x;
            ay += v.y;
        }
    }
    float invd = 1.0f / (float)max(end - row, 1);
    float2 r;
    r.x = ax * invd;
    r.y = ay * invd;
    ((float2*)g_sum1)[(size_t)warp * 32 + lane] = r;
}

// ---------------------------------------------------------------------------
// agg2: one warp per dst node. mean of p2[src] (32 floats; lane = float).
// ---------------------------------------------------------------------------
__global__ __launch_bounds__(256) void agg2_kernel() {
    int warp = (blockIdx.x * blockDim.x + threadIdx.x) >> 5;
    if (warp >= N_NODES) return;
    int lane = threadIdx.x & 31;
    int row = g_rowstart[warp];
    int end = g_rowstart[warp + 1];
    float acc = 0.f;
    for (int base = row; base < end; base += 32) {
        int n = end - base;
        int m = min(n, 32);
        int idx = (lane < m) ? g_csr[base + lane] : 0;
        int k = 0;
        for (; k + 4 <= m; k += 4) {
            int s0 = __shfl_sync(0xffffffffu, idx, k);
            int s1 = __shfl_sync(0xffffffffu, idx, k + 1);
            int s2 = __shfl_sync(0xffffffffu, idx, k + 2);
            int s3 = __shfl_sync(0xffffffffu, idx, k + 3);
            float v0 = g_p2[(size_t)s0 * 32 + lane];
            float v1 = g_p2[(size_t)s1 * 32 + lane];
            float v2 = g_p2[(size_t)s2 * 32 + lane];
            float v3 = g_p2[(size_t)s3 * 32 + lane];
            acc += (v0 + v1) + (v2 + v3);
        }
        for (; k < m; k++) {
            int s = __shfl_sync(0xffffffffu, idx, k);
            acc += g_p2[(size_t)s * 32 + lane];
        }
    }
    float invd = 1.0f / (float)max(end - row, 1);
    g_sum2[(size_t)warp * 32 + lane] = acc * invd;
}

// ---------------------------------------------------------------------------
// GEMM1: h = relu( agg1 @ W1l + x @ W1r + b1l )   (agg1 already the mean)
// ---------------------------------------------------------------------------
__global__ __launch_bounds__(256) void gemm1_kernel(
    const float* __restrict__ x,  const float* __restrict__ W1l,
    const float* __restrict__ b1l, const float* __restrict__ W1r) {
    __shared__ float sA[64 * 128];
    __shared__ float sB[64 * 64];
    int t  = threadIdx.x;
    int cg = t & 15;
    int ng = t >> 4;
    int nodeBase = blockIdx.x * 128;

    float acc[8][4];
#pragma unroll
    for (int m = 0; m < 8; m++)
#pragma unroll
        for (int c = 0; c < 4; c++) acc[m][c] = 0.0f;

    for (int pass = 0; pass < 2; ++pass) {
        const float* A = pass ? x   : g_sum1;
        const float* B = pass ? W1r : W1l;
        __syncthreads();
#pragma unroll
        for (int i = 0; i < 4; i++) {
            int f4 = t + i * 256;
            ((float4*)sB)[f4] = ((const float4*)B)[f4];
        }
#pragma unroll
        for (int i = 0; i < 8; i++) {
            int f4 = t + i * 256;
            int node = f4 >> 4;
            int kq   = f4 & 15;
            int gnode = nodeBase + node;
            float4 v = make_float4(0.f, 0.f, 0.f, 0.f);
            if (gnode < N_NODES)
                v = ((const float4*)(A + (size_t)gnode * 64))[kq];
            int k0 = kq * 4;
            sA[(k0 + 0) * 128 + node] = v.x;
            sA[(k0 + 1) * 128 + node] = v.y;
            sA[(k0 + 2) * 128 + node] = v.z;
            sA[(k0 + 3) * 128 + node] = v.w;
        }
        __syncthreads();
#pragma unroll 8
        for (int k = 0; k < 64; k++) {
            float4 b  = ((const float4*)(sB + k * 64))[cg];
            float4 a0 = ((const float4*)(sA + k * 128))[ng * 2];
            float4 a1 = ((const float4*)(sA + k * 128))[ng * 2 + 1];
            float am[8] = {a0.x, a0.y, a0.z, a0.w, a1.x, a1.y, a1.z, a1.w};
#pragma unroll
            for (int m = 0; m < 8; m++) {
                acc[m][0] = fmaf(am[m], b.x, acc[m][0]);
                acc[m][1] = fmaf(am[m], b.y, acc[m][1]);
                acc[m][2] = fmaf(am[m], b.z, acc[m][2]);
                acc[m][3] = fmaf(am[m], b.w, acc[m][3]);
            }
        }
    }
    float4 bias = ((const float4*)b1l)[cg];
#pragma unroll
    for (int m = 0; m < 8; m++) {
        int node = nodeBase + ng * 8 + m;
        if (node < N_NODES) {
            float4 r;
            r.x = fmaxf(acc[m][0] + bias.x, 0.f);
            r.y = fmaxf(acc[m][1] + bias.y, 0.f);
            r.z = fmaxf(acc[m][2] + bias.z, 0.f);
            r.w = fmaxf(acc[m][3] + bias.w, 0.f);
            ((float4*)(g_h + (size_t)node * 64))[cg] = r;
        }
    }
}

// ---------------------------------------------------------------------------
// GEMM2: p2 = h @ W2l ; out = h @ W2r + b2l  (combined N=64)
// ---------------------------------------------------------------------------
__global__ __launch_bounds__(256) void gemm2_kernel(
    const float* __restrict__ W2l, const float* __restrict__ b2l,
    const float* __restrict__ W2r, float* __restrict__ out) {
    __shared__ float sA[64 * 128];
    __shared__ float sB[64 * 64];
    int t  = threadIdx.x;
    int cg = t & 15;
    int ng = t >> 4;
    int nodeBase = blockIdx.x * 128;

    float acc[8][4];
#pragma unroll
    for (int m = 0; m < 8; m++)
#pragma unroll
        for (int c = 0; c < 4; c++) acc[m][c] = 0.0f;

#pragma unroll
    for (int i = 0; i < 4; i++) {
        int f4 = t + i * 256;
        int k  = f4 >> 4;
        int jq = f4 & 15;
        float4 v = (jq < 8) ? ((const float4*)W2l)[k * 8 + jq]
                            : ((const float4*)W2r)[k * 8 + (jq - 8)];
        ((float4*)sB)[f4] = v;
    }
#pragma unroll
    for (int i = 0; i < 8; i++) {
        int f4 = t + i * 256;
        int node = f4 >> 4;
        int kq   = f4 & 15;
        int gnode = nodeBase + node;
        float4 v = make_float4(0.f, 0.f, 0.f, 0.f);
        if (gnode < N_NODES)
            v = ((const float4*)(g_h + (size_t)gnode * 64))[kq];
        int k0 = kq * 4;
        sA[(k0 + 0) * 128 + node] = v.x;
        sA[(k0 + 1) * 128 + node] = v.y;
        sA[(k0 + 2) * 128 + node] = v.z;
        sA[(k0 + 3) * 128 + node] = v.w;
    }
    __syncthreads();
#pragma unroll 8
    for (int k = 0; k < 64; k++) {
        float4 b  = ((const float4*)(sB + k * 64))[cg];
        float4 a0 = ((const float4*)(sA + k * 128))[ng * 2];
        float4 a1 = ((const float4*)(sA + k * 128))[ng * 2 + 1];
        float am[8] = {a0.x, a0.y, a0.z, a0.w, a1.x, a1.y, a1.z, a1.w};
#pragma unroll
        for (int m = 0; m < 8; m++) {
            acc[m][0] = fmaf(am[m], b.x, acc[m][0]);
            acc[m][1] = fmaf(am[m], b.y, acc[m][1]);
            acc[m][2] = fmaf(am[m], b.z, acc[m][2]);
            acc[m][3] = fmaf(am[m], b.w, acc[m][3]);
        }
    }
#pragma unroll
    for (int m = 0; m < 8; m++) {
        int node = nodeBase + ng * 8 + m;
        if (node < N_NODES) {
            if (cg < 8) {
                float4 r = make_float4(acc[m][0], acc[m][1], acc[m][2], acc[m][3]);
                ((float4*)(g_p2 + (size_t)node * 32))[cg] = r;
            } else {
                float4 bias = ((const float4*)b2l)[cg - 8];
                float4 r;
                r.x = acc[m][0] + bias.x;
                r.y = acc[m][1] + bias.y;
                r.z = acc[m][2] + bias.z;
                r.w = acc[m][3] + bias.w;
                ((float4*)(out + (size_t)node * 32))[cg - 8] = r;
            }
        }
    }
}

// ---------------------------------------------------------------------------
// Final: out[n, :] += mean2[n, :]
// ---------------------------------------------------------------------------
__global__ void final_add_kernel(float* __restrict__ out) {
    unsigned i = blockIdx.x * blockDim.x + threadIdx.x;  // over N*8 float4s
    if (i >= (unsigned)(N_NODES * 8)) return;
    float4 s = ((const float4*)g_sum2)[i];
    float4 o = ((float4*)out)[i];
    o.x += s.x; o.y += s.y; o.z += s.z; o.w += s.w;
    ((float4*)out)[i] = o;
}

extern "C" void kernel_launch(void* const* d_in, const int* in_sizes, int n_in,
                              void* d_out, int out_size) {
    const float* x   = (const float*)d_in[0];
    const void*  ei  = d_in[1];
    const float* W1l = (const float*)d_in[2];
    const float* b1l = (const float*)d_in[3];
    const float* W1r = (const float*)d_in[4];
    const float* W2l = (const float*)d_in[5];
    const float* b2l = (const float*)d_in[6];
    const float* W2r = (const float*)d_in[7];
    float* out = (float*)d_out;
    int E = in_sizes[1] / 2;

    void* p_degi;
    cudaGetSymbolAddress(&p_degi, g_degi);
    cudaMemsetAsync(p_degi, 0, (size_t)N_NODES * sizeof(int), 0);

    detect_dtype_kernel<<<1, 256>>>((const int*)ei);
    {
        int total = 2 * E;
        convert_hist_kernel<<<(total + 255) / 256, 256>>>(ei, E);
    }
    scan_kernel<<<1, 1024>>>();
    fill_kernel<<<(E + 255) / 256, 256>>>(E);

    {   // agg1: one warp per node
        unsigned total = (unsigned)N_NODES * 32u;
        agg1_kernel<<<(total + 255) / 256, 256>>>(x);
    }
    {
        int blocks = (N_NODES + 127) / 128;
        gemm1_kernel<<<blocks, 256>>>(x, W1l, b1l, W1r);
    }
    {
        int blocks = (N_NODES + 127) / 128;
        gemm2_kernel<<<blocks, 256>>>(W2l, b2l, W2r, out);
    }
    {   // agg2
        unsigned total = (unsigned)N_NODES * 32u;
        agg2_kernel<<<(total + 255) / 256, 256>>>();
    }
    {
        unsigned total = N_NODES * 8;
        final_add_kernel<<<(total + 255) / 256, 256>>>(out);
    }
}

// round 4
// speedup vs baseline: 1.0031x; 1.0031x over previous
#include <cuda_runtime.h>
#include <cstdint>

#define N_NODES 100000
#define N_EDGES_MAX 3200000
#define IN_C 64
#define HID_C 64
#define OUT_C 32

// Scratch (static __device__ arrays per harness rules)
__device__ __align__(16) float g_sum1[(size_t)N_NODES * HID_C];   // mean-agg layer1
__device__ __align__(16) float g_h   [(size_t)N_NODES * HID_C];
__device__ __align__(16) float g_p2  [(size_t)N_NODES * OUT_C];
__device__ __align__(16) int   g_eidx[(size_t)2 * N_EDGES_MAX];
__device__ __align__(16) int   g_csr [N_EDGES_MAX];
__device__ __align__(16) int   g_degi[N_NODES];
__device__ __align__(16) int   g_rowstart[N_NODES + 1];
__device__ __align__(16) int   g_cursor[N_NODES];
__device__ int g_is64;

// ---------------------------------------------------------------------------
// Detect int64 vs int32 edge buffer (int64 values < 2^31 -> odd words all 0)
// ---------------------------------------------------------------------------
__global__ void detect_dtype_kernel(const int* __restrict__ ei32) {
    __shared__ int nz;
    if (threadIdx.x == 0) nz = 0;
    __syncthreads();
    int any = 0;
    for (int i = threadIdx.x; i < 8192; i += blockDim.x)
        if (ei32[2 * i + 1] != 0) any = 1;
    if (any) atomicOr(&nz, 1);
    __syncthreads();
    if (threadIdx.x == 0) g_is64 = (nz == 0) ? 1 : 0;
}

// ---------------------------------------------------------------------------
// Convert edges to int32 AND histogram destination degrees. 4 elems/thread.
// ---------------------------------------------------------------------------
__global__ void convert_hist_kernel(const void* __restrict__ ei, int E) {
    int i0 = (blockIdx.x * blockDim.x + threadIdx.x) * 4;
    int is64 = g_is64;
    int v[4];
#pragma unroll
    for (int j = 0; j < 4; j++) {
        int i = i0 + j;
        if (i < 2 * E) {
            v[j] = is64 ? (int)((const long long*)ei)[i] : ((const int*)ei)[i];
            g_eidx[i] = v[j];
        }
    }
#pragma unroll
    for (int j = 0; j < 4; j++) {
        int i = i0 + j;
        if (i >= E && i < 2 * E) atomicAdd(&g_degi[v[j]], 1);
    }
}

// ---------------------------------------------------------------------------
// Single-block exclusive scan of degrees -> rowstart / cursor.
// ---------------------------------------------------------------------------
__global__ __launch_bounds__(1024) void scan_kernel() {
    __shared__ int ssum[1024];
    int t = threadIdx.x;
    const int CH = (N_NODES + 1023) / 1024;   // 98
    int start = t * CH;
    int endi  = min(start + CH, N_NODES);
    int s0 = 0, s1 = 0, s2 = 0, s3 = 0;
    int i = start;
    for (; i + 4 <= endi; i += 4) {
        s0 += g_degi[i];
        s1 += g_degi[i + 1];
        s2 += g_degi[i + 2];
        s3 += g_degi[i + 3];
    }
    for (; i < endi; i++) s0 += g_degi[i];
    ssum[t] = (s0 + s1) + (s2 + s3);
    __syncthreads();
    for (int off = 1; off < 1024; off <<= 1) {
        int v = (t >= off) ? ssum[t - off] : 0;
        __syncthreads();
        ssum[t] += v;
        __syncthreads();
    }
    int prefix = (t == 0) ? 0 : ssum[t - 1];
    for (int k = start; k < endi; k++) {
        g_rowstart[k] = prefix;
        g_cursor[k]   = prefix;
        prefix += g_degi[k];
    }
    if (t == 1023) g_rowstart[N_NODES] = ssum[1023];
}

// ---------------------------------------------------------------------------
// Fill CSR: bucket src indices by dst. 4 edges per thread (MLP=4).
// ---------------------------------------------------------------------------
__global__ void fill_kernel(int E) {
    int e0 = (blockIdx.x * blockDim.x + threadIdx.x) * 4;
    int s[4], d[4];
#pragma unroll
    for (int j = 0; j < 4; j++) {
        int e = e0 + j;
        if (e < E) {
            s[j] = g_eidx[e];
            d[j] = g_eidx[(size_t)E + e];
        }
    }
    int pos[4];
#pragma unroll
    for (int j = 0; j < 4; j++) {
        int e = e0 + j;
        if (e < E) pos[j] = atomicAdd(&g_cursor[d[j]], 1);
    }
#pragma unroll
    for (int j = 0; j < 4; j++) {
        int e = e0 + j;
        if (e < E) g_csr[pos[j]] = s[j];
    }
}

// ---------------------------------------------------------------------------
// agg1: one warp per dst node. mean of x[src] (64 floats; lane = float2).
// Neighbor indices read as uniform (broadcast) global loads; unroll 8.
// ---------------------------------------------------------------------------
__global__ __launch_bounds__(256) void agg1_kernel(const float* __restrict__ x) {
    int warp = (blockIdx.x * blockDim.x + threadIdx.x) >> 5;
    if (warp >= N_NODES) return;
    int lane = threadIdx.x & 31;
    int row = g_rowstart[warp];
    int n   = g_rowstart[warp + 1] - row;
    const int* cs = g_csr + row;
    const float2* x2 = (const float2*)x;
    float a0x = 0.f, a0y = 0.f, a1x = 0.f, a1y = 0.f;
    float a2x = 0.f, a2y = 0.f, a3x = 0.f, a3y = 0.f;
    int k = 0;
    for (; k + 8 <= n; k += 8) {
        int i0 = cs[k + 0], i1 = cs[k + 1], i2 = cs[k + 2], i3 = cs[k + 3];
        int i4 = cs[k + 4], i5 = cs[k + 5], i6 = cs[k + 6], i7 = cs[k + 7];
        float2 v0 = x2[(size_t)i0 * 32 + lane];
        float2 v1 = x2[(size_t)i1 * 32 + lane];
        float2 v2 = x2[(size_t)i2 * 32 + lane];
        float2 v3 = x2[(size_t)i3 * 32 + lane];
        float2 v4 = x2[(size_t)i4 * 32 + lane];
        float2 v5 = x2[(size_t)i5 * 32 + lane];
        float2 v6 = x2[(size_t)i6 * 32 + lane];
        float2 v7 = x2[(size_t)i7 * 32 + lane];
        a0x += v0.x + v1.x; a0y += v0.y + v1.y;
        a1x += v2.x + v3.x; a1y += v2.y + v3.y;
        a2x += v4.x + v5.x; a2y += v4.y + v5.y;
        a3x += v6.x + v7.x; a3y += v6.y + v7.y;
    }
    for (; k < n; k++) {
        int s = cs[k];
        float2 v = x2[(size_t)s * 32 + lane];
        a0x += v.x; a0y += v.y;
    }
    float invd = 1.0f / (float)max(n, 1);
    float2 r;
    r.x = ((a0x + a1x) + (a2x + a3x)) * invd;
    r.y = ((a0y + a1y) + (a2y + a3y)) * invd;
    ((float2*)g_sum1)[(size_t)warp * 32 + lane] = r;
}

// ---------------------------------------------------------------------------
// agg2 + final: one warp per dst node. out[n] += mean of p2[src] (32 floats).
// ---------------------------------------------------------------------------
__global__ __launch_bounds__(256) void agg2_kernel(float* __restrict__ out) {
    int warp = (blockIdx.x * blockDim.x + threadIdx.x) >> 5;
    if (warp >= N_NODES) return;
    int lane = threadIdx.x & 31;
    int row = g_rowstart[warp];
    int n   = g_rowstart[warp + 1] - row;
    const int* cs = g_csr + row;
    float a0 = 0.f, a1 = 0.f, a2 = 0.f, a3 = 0.f;
    int k = 0;
    for (; k + 8 <= n; k += 8) {
        int i0 = cs[k + 0], i1 = cs[k + 1], i2 = cs[k + 2], i3 = cs[k + 3];
        int i4 = cs[k + 4], i5 = cs[k + 5], i6 = cs[k + 6], i7 = cs[k + 7];
        float v0 = g_p2[(size_t)i0 * 32 + lane];
        float v1 = g_p2[(size_t)i1 * 32 + lane];
        float v2 = g_p2[(size_t)i2 * 32 + lane];
        float v3 = g_p2[(size_t)i3 * 32 + lane];
        float v4 = g_p2[(size_t)i4 * 32 + lane];
        float v5 = g_p2[(size_t)i5 * 32 + lane];
        float v6 = g_p2[(size_t)i6 * 32 + lane];
        float v7 = g_p2[(size_t)i7 * 32 + lane];
        a0 += v0 + v1; a1 += v2 + v3; a2 += v4 + v5; a3 += v6 + v7;
    }
    for (; k < n; k++) a0 += g_p2[(size_t)cs[k] * 32 + lane];
    float invd = 1.0f / (float)max(n, 1);
    float total = (a0 + a1) + (a2 + a3);
    size_t oi = (size_t)warp * 32 + lane;
    out[oi] = fmaf(total, invd, out[oi]);
}

// ---------------------------------------------------------------------------
// GEMM1: h = relu( agg1 @ W1l + x @ W1r + b1l )   (agg1 already the mean)
// ---------------------------------------------------------------------------
__global__ __launch_bounds__(256) void gemm1_kernel(
    const float* __restrict__ x,  const float* __restrict__ W1l,
    const float* __restrict__ b1l, const float* __restrict__ W1r) {
    __shared__ float sA[64 * 128];
    __shared__ float sB[64 * 64];
    int t  = threadIdx.x;
    int cg = t & 15;
    int ng = t >> 4;
    int nodeBase = blockIdx.x * 128;

    float acc[8][4];
#pragma unroll
    for (int m = 0; m < 8; m++)
#pragma unroll
        for (int c = 0; c < 4; c++) acc[m][c] = 0.0f;

    for (int pass = 0; pass < 2; ++pass) {
        const float* A = pass ? x   : g_sum1;
        const float* B = pass ? W1r : W1l;
        __syncthreads();
#pragma unroll
        for (int i = 0; i < 4; i++) {
            int f4 = t + i * 256;
            ((float4*)sB)[f4] = ((const float4*)B)[f4];
        }
#pragma unroll
        for (int i = 0; i < 8; i++) {
            int f4 = t + i * 256;
            int node = f4 >> 4;
            int kq   = f4 & 15;
            int gnode = nodeBase + node;
            float4 v = make_float4(0.f, 0.f, 0.f, 0.f);
            if (gnode < N_NODES)
                v = ((const float4*)(A + (size_t)gnode * 64))[kq];
            int k0 = kq * 4;
            sA[(k0 + 0) * 128 + node] = v.x;
            sA[(k0 + 1) * 128 + node] = v.y;
            sA[(k0 + 2) * 128 + node] = v.z;
            sA[(k0 + 3) * 128 + node] = v.w;
        }
        __syncthreads();
#pragma unroll 8
        for (int k = 0; k < 64; k++) {
            float4 b  = ((const float4*)(sB + k * 64))[cg];
            float4 a0 = ((const float4*)(sA + k * 128))[ng * 2];
            float4 a1 = ((const float4*)(sA + k * 128))[ng * 2 + 1];
            float am[8] = {a0.x, a0.y, a0.z, a0.w, a1.x, a1.y, a1.z, a1.w};
#pragma unroll
            for (int m = 0; m < 8; m++) {
                acc[m][0] = fmaf(am[m], b.x, acc[m][0]);
                acc[m][1] = fmaf(am[m], b.y, acc[m][1]);
                acc[m][2] = fmaf(am[m], b.z, acc[m][2]);
                acc[m][3] = fmaf(am[m], b.w, acc[m][3]);
            }
        }
    }
    float4 bias = ((const float4*)b1l)[cg];
#pragma unroll
    for (int m = 0; m < 8; m++) {
        int node = nodeBase + ng * 8 + m;
        if (node < N_NODES) {
            float4 r;
            r.x = fmaxf(acc[m][0] + bias.x, 0.f);
            r.y = fmaxf(acc[m][1] + bias.y, 0.f);
            r.z = fmaxf(acc[m][2] + bias.z, 0.f);
            r.w = fmaxf(acc[m][3] + bias.w, 0.f);
            ((float4*)(g_h + (size_t)node * 64))[cg] = r;
        }
    }
}

// ---------------------------------------------------------------------------
// GEMM2: p2 = h @ W2l ; out = h @ W2r + b2l  (combined N=64)
// ---------------------------------------------------------------------------
__global__ __launch_bounds__(256) void gemm2_kernel(
    const float* __restrict__ W2l, const float* __restrict__ b2l,
    const float* __restrict__ W2r, float* __restrict__ out) {
    __shared__ float sA[64 * 128];
    __shared__ float sB[64 * 64];
    int t  = threadIdx.x;
    int cg = t & 15;
    int ng = t >> 4;
    int nodeBase = blockIdx.x * 128;

    float acc[8][4];
#pragma unroll
    for (int m = 0; m < 8; m++)
#pragma unroll
        for (int c = 0; c < 4; c++) acc[m][c] = 0.0f;

#pragma unroll
    for (int i = 0; i < 4; i++) {
        int f4 = t + i * 256;
        int k  = f4 >> 4;
        int jq = f4 & 15;
        float4 v = (jq < 8) ? ((const float4*)W2l)[k * 8 + jq]
                            : ((const float4*)W2r)[k * 8 + (jq - 8)];
        ((float4*)sB)[f4] = v;
    }
#pragma unroll
    for (int i = 0; i < 8; i++) {
        int f4 = t + i * 256;
        int node = f4 >> 4;
        int kq   = f4 & 15;
        int gnode = nodeBase + node;
        float4 v = make_float4(0.f, 0.f, 0.f, 0.f);
        if (gnode < N_NODES)
            v = ((const float4*)(g_h + (size_t)gnode * 64))[kq];
        int k0 = kq * 4;
        sA[(k0 + 0) * 128 + node] = v.x;
        sA[(k0 + 1) * 128 + node] = v.y;
        sA[(k0 + 2) * 128 + node] = v.z;
        sA[(k0 + 3) * 128 + node] = v.w;
    }
    __syncthreads();
#pragma unroll 8
    for (int k = 0; k < 64; k++) {
        float4 b  = ((const float4*)(sB + k * 64))[cg];
        float4 a0 = ((const float4*)(sA + k * 128))[ng * 2];
        float4 a1 = ((const float4*)(sA + k * 128))[ng * 2 + 1];
        float am[8] = {a0.x, a0.y, a0.z, a0.w, a1.x, a1.y, a1.z, a1.w};
#pragma unroll
        for (int m = 0; m < 8; m++) {
            acc[m][0] = fmaf(am[m], b.x, acc[m][0]);
            acc[m][1] = fmaf(am[m], b.y, acc[m][1]);
            acc[m][2] = fmaf(am[m], b.z, acc[m][2]);
            acc[m][3] = fmaf(am[m], b.w, acc[m][3]);
        }
    }
#pragma unroll
    for (int m = 0; m < 8; m++) {
        int node = nodeBase + ng * 8 + m;
        if (node < N_NODES) {
            if (cg < 8) {
                float4 r = make_float4(acc[m][0], acc[m][1], acc[m][2], acc[m][3]);
                ((float4*)(g_p2 + (size_t)node * 32))[cg] = r;
            } else {
                float4 bias = ((const float4*)b2l)[cg - 8];
                float4 r;
                r.x = acc[m][0] + bias.x;
                r.y = acc[m][1] + bias.y;
                r.z = acc[m][2] + bias.z;
                r.w = acc[m][3] + bias.w;
                ((float4*)(out + (size_t)node * 32))[cg - 8] = r;
            }
        }
    }
}

extern "C" void kernel_launch(void* const* d_in, const int* in_sizes, int n_in,
                              void* d_out, int out_size) {
    const float* x   = (const float*)d_in[0];
    const void*  ei  = d_in[1];
    const float* W1l = (const float*)d_in[2];
    const float* b1l = (const float*)d_in[3];
    const float* W1r = (const float*)d_in[4];
    const float* W2l = (const float*)d_in[5];
    const float* b2l = (const float*)d_in[6];
    const float* W2r = (const float*)d_in[7];
    float* out = (float*)d_out;
    int E = in_sizes[1] / 2;

    void* p_degi;
    cudaGetSymbolAddress(&p_degi, g_degi);
    cudaMemsetAsync(p_degi, 0, (size_t)N_NODES * sizeof(int), 0);

    detect_dtype_kernel<<<1, 256>>>((const int*)ei);
    {
        int threads = (2 * E + 3) / 4;
        convert_hist_kernel<<<(threads + 255) / 256, 256>>>(ei, E);
    }
    scan_kernel<<<1, 1024>>>();
    {
        int threads = (E + 3) / 4;
        fill_kernel<<<(threads + 255) / 256, 256>>>(E);
    }
    {   // agg1: one warp per node
        unsigned total = (unsigned)N_NODES * 32u;
        agg1_kernel<<<(total + 255) / 256, 256>>>(x);
    }
    {
        int blocks = (N_NODES + 127) / 128;
        gemm1_kernel<<<blocks, 256>>>(x, W1l, b1l, W1r);
    }
    {
        int blocks = (N_NODES + 127) / 128;
        gemm2_kernel<<<blocks, 256>>>(W2l, b2l, W2r, out);
    }
    {   // agg2 + final add fused
        unsigned total = (unsigned)N_NODES * 32u;
        agg2_kernel<<<(total + 255) / 256, 256>>>(out);
    }
}

// round 6
// speedup vs baseline: 1.0481x; 1.0449x over previous
#include <cuda_runtime.h>
#include <cuda_fp16.h>
#include <cstdint>

#define N_NODES 100000
#define N_EDGES_MAX 3200000
#define IN_C 64
#define HID_C 64
#define OUT_C 32

// Scratch (static __device__ arrays per harness rules)
__device__ __align__(16) float  g_sum1[(size_t)N_NODES * HID_C];  // mean-agg L1
__device__ __align__(16) float  g_h   [(size_t)N_NODES * HID_C];
__device__ __align__(16) __half g_xh  [(size_t)N_NODES * IN_C];   // x in fp16
__device__ __align__(16) __half g_p2h [(size_t)N_NODES * OUT_C];  // h@W2l fp16
__device__ __align__(16) int    g_csr [N_EDGES_MAX];
__device__ __align__(16) int    g_degi[N_NODES];
__device__ __align__(16) int    g_rowstart[N_NODES + 1];
__device__ __align__(16) int    g_cursor[N_NODES];

static __device__ __forceinline__ unsigned h2_bits(__half2 h) {
    return *reinterpret_cast<const unsigned*>(&h);
}

// ---------------------------------------------------------------------------
// Kernel 1: degree histogram (dst half of edge_index) + x -> fp16 convert.
// One thread: 4 edges + 8 x-floats.
// ---------------------------------------------------------------------------
__global__ void hist_xconv_kernel(const int* __restrict__ ei,
                                  const float* __restrict__ x, int E) {
    int t = blockIdx.x * blockDim.x + threadIdx.x;
    int e0 = t * 4;
    int d[4];
#pragma unroll
    for (int j = 0; j < 4; j++) {
        int e = e0 + j;
        if (e < E) d[j] = ei[(size_t)E + e];
    }
#pragma unroll
    for (int j = 0; j < 4; j++) {
        int e = e0 + j;
        if (e < E) atomicAdd(&g_degi[d[j]], 1);
    }
    // x convert: 8 floats -> 4 half2 (one 16B store)
    size_t xi = (size_t)t * 8;
    if (xi + 8 <= (size_t)N_NODES * IN_C) {
        float4 f0 = ((const float4*)x)[t * 2];
        float4 f1 = ((const float4*)x)[t * 2 + 1];
        __half2 h0 = __floats2half2_rn(f0.x, f0.y);
        __half2 h1 = __floats2half2_rn(f0.z, f0.w);
        __half2 h2 = __floats2half2_rn(f1.x, f1.y);
        __half2 h3 = __floats2half2_rn(f1.z, f1.w);
        uint4 packed = make_uint4(h2_bits(h0), h2_bits(h1), h2_bits(h2), h2_bits(h3));
        ((uint4*)g_xh)[t] = packed;
    }
}

// ---------------------------------------------------------------------------
// Kernel 2: single-block exclusive scan of degrees -> rowstart / cursor.
// ---------------------------------------------------------------------------
__global__ __launch_bounds__(1024) void scan_kernel() {
    __shared__ int ssum[1024];
    int t = threadIdx.x;
    const int CH = (N_NODES + 1023) / 1024;   // 98
    int start = t * CH;
    int endi  = min(start + CH, N_NODES);
    int s0 = 0, s1 = 0, s2 = 0, s3 = 0;
    int i = start;
    for (; i + 4 <= endi; i += 4) {
        s0 += g_degi[i];
        s1 += g_degi[i + 1];
        s2 += g_degi[i + 2];
        s3 += g_degi[i + 3];
    }
    for (; i < endi; i++) s0 += g_degi[i];
    ssum[t] = (s0 + s1) + (s2 + s3);
    __syncthreads();
    for (int off = 1; off < 1024; off <<= 1) {
        int v = (t >= off) ? ssum[t - off] : 0;
        __syncthreads();
        ssum[t] += v;
        __syncthreads();
    }
    int prefix = (t == 0) ? 0 : ssum[t - 1];
    for (int k = start; k < endi; k++) {
        g_rowstart[k] = prefix;
        g_cursor[k]   = prefix;
        prefix += g_degi[k];
    }
    if (t == 1023) g_rowstart[N_NODES] = ssum[1023];
}

// ---------------------------------------------------------------------------
// Kernel 3: fill CSR (bucket src by dst). 4 edges per thread.
// ---------------------------------------------------------------------------
__global__ void fill_kernel(const int* __restrict__ ei, int E) {
    int e0 = (blockIdx.x * blockDim.x + threadIdx.x) * 4;
    int s[4], d[4];
#pragma unroll
    for (int j = 0; j < 4; j++) {
        int e = e0 + j;
        if (e < E) {
            s[j] = ei[e];
            d[j] = ei[(size_t)E + e];
        }
    }
    int pos[4];
#pragma unroll
    for (int j = 0; j < 4; j++) {
        int e = e0 + j;
        if (e < E) pos[j] = atomicAdd(&g_cursor[d[j]], 1);
    }
#pragma unroll
    for (int j = 0; j < 4; j++) {
        int e = e0 + j;
        if (e < E) g_csr[pos[j]] = s[j];
    }
}

// ---------------------------------------------------------------------------
// Kernel 4 (PROFILED SLOT): agg1 — one warp per dst node.
// mean of xh[src] (64 half; lane = half2). fp32 accumulation.
// ---------------------------------------------------------------------------
__global__ __launch_bounds__(256) void agg1_kernel() {
    int warp = (blockIdx.x * blockDim.x + threadIdx.x) >> 5;
    if (warp >= N_NODES) return;
    int lane = threadIdx.x & 31;
    int row = g_rowstart[warp];
    int n   = g_rowstart[warp + 1] - row;
    const int* cs = g_csr + row;
    const __half2* xh2 = (const __half2*)g_xh;
    float a0x = 0.f, a0y = 0.f, a1x = 0.f, a1y = 0.f;
    float a2x = 0.f, a2y = 0.f, a3x = 0.f, a3y = 0.f;
    int k = 0;
    for (; k + 8 <= n; k += 8) {
        int i0 = cs[k + 0], i1 = cs[k + 1], i2 = cs[k + 2], i3 = cs[k + 3];
        int i4 = cs[k + 4], i5 = cs[k + 5], i6 = cs[k + 6], i7 = cs[k + 7];
        float2 v0 = __half22float2(xh2[(size_t)i0 * 32 + lane]);
        float2 v1 = __half22float2(xh2[(size_t)i1 * 32 + lane]);
        float2 v2 = __half22float2(xh2[(size_t)i2 * 32 + lane]);
        float2 v3 = __half22float2(xh2[(size_t)i3 * 32 + lane]);
        float2 v4 = __half22float2(xh2[(size_t)i4 * 32 + lane]);
        float2 v5 = __half22float2(xh2[(size_t)i5 * 32 + lane]);
        float2 v6 = __half22float2(xh2[(size_t)i6 * 32 + lane]);
        float2 v7 = __half22float2(xh2[(size_t)i7 * 32 + lane]);
        a0x += v0.x + v1.x; a0y += v0.y + v1.y;
        a1x += v2.x + v3.x; a1y += v2.y + v3.y;
        a2x += v4.x + v5.x; a2y += v4.y + v5.y;
        a3x += v6.x + v7.x; a3y += v6.y + v7.y;
    }
    for (; k < n; k++) {
        float2 v = __half22float2(xh2[(size_t)cs[k] * 32 + lane]);
        a0x += v.x; a0y += v.y;
    }
    float invd = 1.0f / (float)max(n, 1);
    float2 r;
    r.x = ((a0x + a1x) + (a2x + a3x)) * invd;
    r.y = ((a0y + a1y) + (a2y + a3y)) * invd;
    ((float2*)g_sum1)[(size_t)warp * 32 + lane] = r;
}

// ---------------------------------------------------------------------------
// Kernel 5: GEMM1  h = relu( sum1 @ W1l + x @ W1r + b1l )
// 256 thr, tile 128 nodes x 64 cols; thread tile 8 nodes x 4 cols.
// A read directly from global as float4 along k; B staged in smem.
// ---------------------------------------------------------------------------
__global__ __launch_bounds__(256) void gemm1_kernel(
    const float* __restrict__ x,  const float* __restrict__ W1l,
    const float* __restrict__ b1l, const float* __restrict__ W1r) {
    __shared__ float sB[64 * 64];
    int t  = threadIdx.x;
    int cg = t & 15;   // cols 4*cg..4*cg+3
    int ng = t >> 4;   // nodes 8*ng..8*ng+7
    int nodeBase = blockIdx.x * 128 + ng * 8;

    float acc[8][4];
#pragma unroll
    for (int m = 0; m < 8; m++)
#pragma unroll
        for (int c = 0; c < 4; c++) acc[m][c] = 0.0f;

    for (int pass = 0; pass < 2; ++pass) {
        const float4* A4 = (const float4*)(pass ? x : g_sum1);
        const float*  B  = pass ? W1r : W1l;
        __syncthreads();
#pragma unroll
        for (int i = 0; i < 4; i++) {
            int f4 = t + i * 256;
            ((float4*)sB)[f4] = ((const float4*)B)[f4];
        }
        __syncthreads();
        const float4* sB4 = (const float4*)sB;
#pragma unroll 4
        for (int k4 = 0; k4 < 16; k4++) {
            float4 b0 = sB4[(k4 * 4 + 0) * 16 + cg];
            float4 b1 = sB4[(k4 * 4 + 1) * 16 + cg];
            float4 b2 = sB4[(k4 * 4 + 2) * 16 + cg];
            float4 b3 = sB4[(k4 * 4 + 3) * 16 + cg];
#pragma unroll
            for (int m = 0; m < 8; m++) {
                int node = min(nodeBase + m, N_NODES - 1);
                float4 a = A4[(size_t)node * 16 + k4];
                acc[m][0] = fmaf(a.x, b0.x, acc[m][0]);
                acc[m][1] = fmaf(a.x, b0.y, acc[m][1]);
                acc[m][2] = fmaf(a.x, b0.z, acc[m][2]);
                acc[m][3] = fmaf(a.x, b0.w, acc[m][3]);
                acc[m][0] = fmaf(a.y, b1.x, acc[m][0]);
                acc[m][1] = fmaf(a.y, b1.y, acc[m][1]);
                acc[m][2] = fmaf(a.y, b1.z, acc[m][2]);
                acc[m][3] = fmaf(a.y, b1.w, acc[m][3]);
                acc[m][0] = fmaf(a.z, b2.x, acc[m][0]);
                acc[m][1] = fmaf(a.z, b2.y, acc[m][1]);
                acc[m][2] = fmaf(a.z, b2.z, acc[m][2]);
                acc[m][3] = fmaf(a.z, b2.w, acc[m][3]);
                acc[m][0] = fmaf(a.w, b3.x, acc[m][0]);
                acc[m][1] = fmaf(a.w, b3.y, acc[m][1]);
                acc[m][2] = fmaf(a.w, b3.z, acc[m][2]);
                acc[m][3] = fmaf(a.w, b3.w, acc[m][3]);
            }
        }
    }
    float4 bias = ((const float4*)b1l)[cg];
#pragma unroll
    for (int m = 0; m < 8; m++) {
        int node = nodeBase + m;
        if (node < N_NODES) {
            float4 r;
            r.x = fmaxf(acc[m][0] + bias.x, 0.f);
            r.y = fmaxf(acc[m][1] + bias.y, 0.f);
            r.z = fmaxf(acc[m][2] + bias.z, 0.f);
            r.w = fmaxf(acc[m][3] + bias.w, 0.f);
            ((float4*)(g_h + (size_t)node * 64))[cg] = r;
        }
    }
}

// ---------------------------------------------------------------------------
// Kernel 6: GEMM2  p2h = (h @ W2l) as fp16 ; out = h @ W2r + b2l
// Combined 64-col B tile: cols 0-31 = W2l, 32-63 = W2r.
// ---------------------------------------------------------------------------
__global__ __launch_bounds__(256) void gemm2_kernel(
    const float* __restrict__ W2l, const float* __restrict__ b2l,
    const float* __restrict__ W2r, float* __restrict__ out) {
    __shared__ float sB[64 * 64];
    int t  = threadIdx.x;
    int cg = t & 15;
    int ng = t >> 4;
    int nodeBase = blockIdx.x * 128 + ng * 8;

    float acc[8][4];
#pragma unroll
    for (int m = 0; m < 8; m++)
#pragma unroll
        for (int c = 0; c < 4; c++) acc[m][c] = 0.0f;

#pragma unroll
    for (int i = 0; i < 4; i++) {
        int f4 = t + i * 256;
        int k  = f4 >> 4;
        int jq = f4 & 15;
        float4 v = (jq < 8) ? ((const float4*)W2l)[k * 8 + jq]
                            : ((const float4*)W2r)[k * 8 + (jq - 8)];
        ((float4*)sB)[f4] = v;
    }
    __syncthreads();
    const float4* A4  = (const float4*)g_h;
    const float4* sB4 = (const float4*)sB;
#pragma unroll 4
    for (int k4 = 0; k4 < 16; k4++) {
        float4 b0 = sB4[(k4 * 4 + 0) * 16 + cg];
        float4 b1 = sB4[(k4 * 4 + 1) * 16 + cg];
        float4 b2 = sB4[(k4 * 4 + 2) * 16 + cg];
        float4 b3 = sB4[(k4 * 4 + 3) * 16 + cg];
#pragma unroll
        for (int m = 0; m < 8; m++) {
            int node = min(nodeBase + m, N_NODES - 1);
            float4 a = A4[(size_t)node * 16 + k4];
            acc[m][0] = fmaf(a.x, b0.x, acc[m][0]);
            acc[m][1] = fmaf(a.x, b0.y, acc[m][1]);
            acc[m][2] = fmaf(a.x, b0.z, acc[m][2]);
            acc[m][3] = fmaf(a.x, b0.w, acc[m][3]);
            acc[m][0] = fmaf(a.y, b1.x, acc[m][0]);
            acc[m][1] = fmaf(a.y, b1.y, acc[m][1]);
            acc[m][2] = fmaf(a.y, b1.z, acc[m][2]);
            acc[m][3] = fmaf(a.y, b1.w, acc[m][3]);
            acc[m][0] = fmaf(a.z, b2.x, acc[m][0]);
            acc[m][1] = fmaf(a.z, b2.y, acc[m][1]);
            acc[m][2] = fmaf(a.z, b2.z, acc[m][2]);
            acc[m][3] = fmaf(a.z, b2.w, acc[m][3]);
            acc[m][0] = fmaf(a.w, b3.x, acc[m][0]);
            acc[m][1] = fmaf(a.w, b3.y, acc[m][1]);
            acc[m][2] = fmaf(a.w, b3.z, acc[m][2]);
            acc[m][3] = fmaf(a.w, b3.w, acc[m][3]);
        }
    }
#pragma unroll
    for (int m = 0; m < 8; m++) {
        int node = nodeBase + m;
        if (node < N_NODES) {
            if (cg < 8) {   // p2 -> fp16 (one 16B store of 8 half)
                __half2 h0 = __floats2half2_rn(acc[m][0], acc[m][1]);
                __half2 h1 = __floats2half2_rn(acc[m][2], acc[m][3]);
                uint2 packed = make_uint2(h2_bits(h0), h2_bits(h1));
                ((uint2*)(g_p2h + (size_t)node * 32))[cg] = packed;
            } else {        // out = h @ W2r + b2l
                float4 bias = ((const float4*)b2l)[cg - 8];
                float4 r;
                r.x = acc[m][0] + bias.x;
                r.y = acc[m][1] + bias.y;
                r.z = acc[m][2] + bias.z;
                r.w = acc[m][3] + bias.w;
                ((float4*)(out + (size_t)node * 32))[cg - 8] = r;
            }
        }
    }
}

// ---------------------------------------------------------------------------
// Kernel 7: agg2 + final — one warp per dst node. out += mean of p2h[src].
// ---------------------------------------------------------------------------
__global__ __launch_bounds__(256) void agg2_kernel(float* __restrict__ out) {
    int warp = (blockIdx.x * blockDim.x + threadIdx.x) >> 5;
    if (warp >= N_NODES) return;
    int lane = threadIdx.x & 31;
    int row = g_rowstart[warp];
    int n   = g_rowstart[warp + 1] - row;
    const int* cs = g_csr + row;
    float a0 = 0.f, a1 = 0.f, a2 = 0.f, a3 = 0.f;
    int k = 0;
    for (; k + 8 <= n; k += 8) {
        int i0 = cs[k + 0], i1 = cs[k + 1], i2 = cs[k + 2], i3 = cs[k + 3];
        int i4 = cs[k + 4], i5 = cs[k + 5], i6 = cs[k + 6], i7 = cs[k + 7];
        float v0 = __half2float(g_p2h[(size_t)i0 * 32 + lane]);
        float v1 = __half2float(g_p2h[(size_t)i1 * 32 + lane]);
        float v2 = __half2float(g_p2h[(size_t)i2 * 32 + lane]);
        float v3 = __half2float(g_p2h[(size_t)i3 * 32 + lane]);
        float v4 = __half2float(g_p2h[(size_t)i4 * 32 + lane]);
        float v5 = __half2float(g_p2h[(size_t)i5 * 32 + lane]);
        float v6 = __half2float(g_p2h[(size_t)i6 * 32 + lane]);
        float v7 = __half2float(g_p2h[(size_t)i7 * 32 + lane]);
        a0 += v0 + v1; a1 += v2 + v3; a2 += v4 + v5; a3 += v6 + v7;
    }
    for (; k < n; k++) a0 += __half2float(g_p2h[(size_t)cs[k] * 32 + lane]);
    float invd = 1.0f / (float)max(n, 1);
    float total = (a0 + a1) + (a2 + a3);
    size_t oi = (size_t)warp * 32 + lane;
    out[oi] = fmaf(total, invd, out[oi]);
}

extern "C" void kernel_launch(void* const* d_in, const int* in_sizes, int n_in,
                              void* d_out, int out_size) {
    const float* x   = (const float*)d_in[0];
    const int*   ei  = (const int*)d_in[1];   // int32 (established in R1/R2)
    const float* W1l = (const float*)d_in[2];
    const float* b1l = (const float*)d_in[3];
    const float* W1r = (const float*)d_in[4];
    const float* W2l = (const float*)d_in[5];
    const float* b2l = (const float*)d_in[6];
    const float* W2r = (const float*)d_in[7];
    float* out = (float*)d_out;
    int E = in_sizes[1] / 2;

    void* p_degi;
    cudaGetSymbolAddress(&p_degi, g_degi);
    cudaMemsetAsync(p_degi, 0, (size_t)N_NODES * sizeof(int), 0);

    {   // kernel 1: hist + x->fp16
        int tE = (E + 3) / 4;
        int tX = (N_NODES * IN_C + 7) / 8;
        int threads = tE > tX ? tE : tX;
        hist_xconv_kernel<<<(threads + 255) / 256, 256>>>(ei, x, E);
    }
    scan_kernel<<<1, 1024>>>();                       // kernel 2
    {
        int threads = (E + 3) / 4;                    // kernel 3
        fill_kernel<<<(threads + 255) / 256, 256>>>(ei, E);
    }
    {   // kernel 4 (profiled): agg1
        unsigned total = (unsigned)N_NODES * 32u;
        agg1_kernel<<<(total + 255) / 256, 256>>>();
    }
    {
        int blocks = (N_NODES + 127) / 128;           // kernel 5
        gemm1_kernel<<<blocks, 256>>>(x, W1l, b1l, W1r);
    }
    {
        int blocks = (N_NODES + 127) / 128;           // kernel 6
        gemm2_kernel<<<blocks, 256>>>(W2l, b2l, W2r, out);
    }
    {   // kernel 7: agg2 + final add
        unsigned total = (unsigned)N_NODES * 32u;
        agg2_kernel<<<(total + 255) / 256, 256>>>(out);
    }
}

// round 7
// speedup vs baseline: 1.2212x; 1.1651x over previous
#include <cuda_runtime.h>
#include <cuda_fp16.h>
#include <cstdint>

#define N_NODES 100000
#define N_EDGES_MAX 3200000
#define IN_C 64
#define HID_C 64
#define OUT_C 32

// Scratch (static __device__ arrays per harness rules)
__device__ __align__(16) float  g_sum1[(size_t)N_NODES * HID_C];  // mean-agg L1
__device__ __align__(16) float  g_h   [(size_t)N_NODES * HID_C];
__device__ __align__(16) __half g_xh  [(size_t)N_NODES * IN_C];   // x in fp16
__device__ __align__(16) __half g_p2h [(size_t)N_NODES * OUT_C];  // h@W2l fp16
__device__ __align__(16) int    g_csr [N_EDGES_MAX];
__device__ __align__(16) int    g_rank[N_EDGES_MAX];              // rank within dst bucket
__device__ __align__(16) int    g_degi[N_NODES];
__device__ __align__(16) int    g_rowstart[N_NODES + 1];

static __device__ __forceinline__ unsigned h2_bits(__half2 h) {
    return *reinterpret_cast<const unsigned*>(&h);
}

// ---------------------------------------------------------------------------
// Kernel 1: degree histogram + per-edge rank (atomic return) + x -> fp16.
// One thread: 4 edges + 8 x-floats.
// ---------------------------------------------------------------------------
__global__ void hist_xconv_kernel(const int* __restrict__ ei,
                                  const float* __restrict__ x, int E) {
    int t = blockIdx.x * blockDim.x + threadIdx.x;
    int e0 = t * 4;
    int d[4];
#pragma unroll
    for (int j = 0; j < 4; j++) {
        int e = e0 + j;
        if (e < E) d[j] = ei[(size_t)E + e];
    }
    int r[4];
#pragma unroll
    for (int j = 0; j < 4; j++) {
        int e = e0 + j;
        if (e < E) r[j] = atomicAdd(&g_degi[d[j]], 1);
    }
#pragma unroll
    for (int j = 0; j < 4; j++) {
        int e = e0 + j;
        if (e < E) g_rank[e] = r[j];
    }
    // x convert: 8 floats -> 4 half2 (one 16B store)
    size_t xi = (size_t)t * 8;
    if (xi + 8 <= (size_t)N_NODES * IN_C) {
        float4 f0 = ((const float4*)x)[t * 2];
        float4 f1 = ((const float4*)x)[t * 2 + 1];
        __half2 h0 = __floats2half2_rn(f0.x, f0.y);
        __half2 h1 = __floats2half2_rn(f0.z, f0.w);
        __half2 h2 = __floats2half2_rn(f1.x, f1.y);
        __half2 h3 = __floats2half2_rn(f1.z, f1.w);
        uint4 packed = make_uint4(h2_bits(h0), h2_bits(h1), h2_bits(h2), h2_bits(h3));
        ((uint4*)g_xh)[t] = packed;
    }
}

// ---------------------------------------------------------------------------
// Kernel 2: single-block exclusive scan of degrees -> rowstart.
// ---------------------------------------------------------------------------
__global__ __launch_bounds__(1024) void scan_kernel() {
    __shared__ int ssum[1024];
    int t = threadIdx.x;
    const int CH = (N_NODES + 1023) / 1024;   // 98
    int start = t * CH;
    int endi  = min(start + CH, N_NODES);
    int s0 = 0, s1 = 0, s2 = 0, s3 = 0;
    int i = start;
    for (; i + 4 <= endi; i += 4) {
        s0 += g_degi[i];
        s1 += g_degi[i + 1];
        s2 += g_degi[i + 2];
        s3 += g_degi[i + 3];
    }
    for (; i < endi; i++) s0 += g_degi[i];
    ssum[t] = (s0 + s1) + (s2 + s3);
    __syncthreads();
    for (int off = 1; off < 1024; off <<= 1) {
        int v = (t >= off) ? ssum[t - off] : 0;
        __syncthreads();
        ssum[t] += v;
        __syncthreads();
    }
    int prefix = (t == 0) ? 0 : ssum[t - 1];
    for (int k = start; k < endi; k++) {
        g_rowstart[k] = prefix;
        prefix += g_degi[k];
    }
    if (t == 1023) g_rowstart[N_NODES] = ssum[1023];
}

// ---------------------------------------------------------------------------
// Kernel 3: fill CSR — NO atomics: pos = rowstart[dst] + rank[e].
// 4 edges per thread.
// ---------------------------------------------------------------------------
__global__ void fill_kernel(const int* __restrict__ ei, int E) {
    int e0 = (blockIdx.x * blockDim.x + threadIdx.x) * 4;
    int s[4], d[4], r[4];
#pragma unroll
    for (int j = 0; j < 4; j++) {
        int e = e0 + j;
        if (e < E) {
            s[j] = ei[e];
            d[j] = ei[(size_t)E + e];
            r[j] = g_rank[e];
        }
    }
    int base[4];
#pragma unroll
    for (int j = 0; j < 4; j++) {
        int e = e0 + j;
        if (e < E) base[j] = g_rowstart[d[j]];
    }
#pragma unroll
    for (int j = 0; j < 4; j++) {
        int e = e0 + j;
        if (e < E) g_csr[base[j] + r[j]] = s[j];
    }
}

// ---------------------------------------------------------------------------
// Kernel 4 (PROFILED SLOT): agg1 — one warp per dst node.
// mean of xh[src] (64 half; lane = half2). fp32 accumulation.
// 32-bit address arithmetic.
// ---------------------------------------------------------------------------
__global__ __launch_bounds__(256) void agg1_kernel() {
    int warp = (blockIdx.x * blockDim.x + threadIdx.x) >> 5;
    if (warp >= N_NODES) return;
    unsigned lane = threadIdx.x & 31;
    int row = g_rowstart[warp];
    int n   = g_rowstart[warp + 1] - row;
    const int* cs = g_csr + row;
    const __half2* xh2 = (const __half2*)g_xh;
    float a0x = 0.f, a0y = 0.f, a1x = 0.f, a1y = 0.f;
    float a2x = 0.f, a2y = 0.f, a3x = 0.f, a3y = 0.f;
    int k = 0;
    for (; k + 8 <= n; k += 8) {
        unsigned o0 = (unsigned)cs[k + 0] * 32u + lane;
        unsigned o1 = (unsigned)cs[k + 1] * 32u + lane;
        unsigned o2 = (unsigned)cs[k + 2] * 32u + lane;
        unsigned o3 = (unsigned)cs[k + 3] * 32u + lane;
        unsigned o4 = (unsigned)cs[k + 4] * 32u + lane;
        unsigned o5 = (unsigned)cs[k + 5] * 32u + lane;
        unsigned o6 = (unsigned)cs[k + 6] * 32u + lane;
        unsigned o7 = (unsigned)cs[k + 7] * 32u + lane;
        float2 v0 = __half22float2(xh2[o0]);
        float2 v1 = __half22float2(xh2[o1]);
        float2 v2 = __half22float2(xh2[o2]);
        float2 v3 = __half22float2(xh2[o3]);
        float2 v4 = __half22float2(xh2[o4]);
        float2 v5 = __half22float2(xh2[o5]);
        float2 v6 = __half22float2(xh2[o6]);
        float2 v7 = __half22float2(xh2[o7]);
        a0x += v0.x + v1.x; a0y += v0.y + v1.y;
        a1x += v2.x + v3.x; a1y += v2.y + v3.y;
        a2x += v4.x + v5.x; a2y += v4.y + v5.y;
        a3x += v6.x + v7.x; a3y += v6.y + v7.y;
    }
    for (; k < n; k++) {
        float2 v = __half22float2(xh2[(unsigned)cs[k] * 32u + lane]);
        a0x += v.x; a0y += v.y;
    }
    float invd = 1.0f / (float)max(n, 1);
    float2 r;
    r.x = ((a0x + a1x) + (a2x + a3x)) * invd;
    r.y = ((a0y + a1y) + (a2y + a3y)) * invd;
    ((float2*)g_sum1)[(unsigned)warp * 32u + lane] = r;
}

// ---------------------------------------------------------------------------
// Kernel 5: GEMM1  h = relu( sum1 @ W1l + x @ W1r + b1l )
// ---------------------------------------------------------------------------
__global__ __launch_bounds__(256) void gemm1_kernel(
    const float* __restrict__ x,  const float* __restrict__ W1l,
    const float* __restrict__ b1l, const float* __restrict__ W1r) {
    __shared__ float sB[64 * 64];
    int t  = threadIdx.x;
    int cg = t & 15;   // cols 4*cg..4*cg+3
    int ng = t >> 4;   // nodes 8*ng..8*ng+7
    int nodeBase = blockIdx.x * 128 + ng * 8;

    float acc[8][4];
#pragma unroll
    for (int m = 0; m < 8; m++)
#pragma unroll
        for (int c = 0; c < 4; c++) acc[m][c] = 0.0f;

    for (int pass = 0; pass < 2; ++pass) {
        const float4* A4 = (const float4*)(pass ? x : g_sum1);
        const float*  B  = pass ? W1r : W1l;
        __syncthreads();
#pragma unroll
        for (int i = 0; i < 4; i++) {
            int f4 = t + i * 256;
            ((float4*)sB)[f4] = ((const float4*)B)[f4];
        }
        __syncthreads();
        const float4* sB4 = (const float4*)sB;
#pragma unroll 4
        for (int k4 = 0; k4 < 16; k4++) {
            float4 b0 = sB4[(k4 * 4 + 0) * 16 + cg];
            float4 b1 = sB4[(k4 * 4 + 1) * 16 + cg];
            float4 b2 = sB4[(k4 * 4 + 2) * 16 + cg];
            float4 b3 = sB4[(k4 * 4 + 3) * 16 + cg];
#pragma unroll
            for (int m = 0; m < 8; m++) {
                int node = min(nodeBase + m, N_NODES - 1);
                float4 a = A4[(size_t)node * 16 + k4];
                acc[m][0] = fmaf(a.x, b0.x, acc[m][0]);
                acc[m][1] = fmaf(a.x, b0.y, acc[m][1]);
                acc[m][2] = fmaf(a.x, b0.z, acc[m][2]);
                acc[m][3] = fmaf(a.x, b0.w, acc[m][3]);
                acc[m][0] = fmaf(a.y, b1.x, acc[m][0]);
                acc[m][1] = fmaf(a.y, b1.y, acc[m][1]);
                acc[m][2] = fmaf(a.y, b1.z, acc[m][2]);
                acc[m][3] = fmaf(a.y, b1.w, acc[m][3]);
                acc[m][0] = fmaf(a.z, b2.x, acc[m][0]);
                acc[m][1] = fmaf(a.z, b2.y, acc[m][1]);
                acc[m][2] = fmaf(a.z, b2.z, acc[m][2]);
                acc[m][3] = fmaf(a.z, b2.w, acc[m][3]);
                acc[m][0] = fmaf(a.w, b3.x, acc[m][0]);
                acc[m][1] = fmaf(a.w, b3.y, acc[m][1]);
                acc[m][2] = fmaf(a.w, b3.z, acc[m][2]);
                acc[m][3] = fmaf(a.w, b3.w, acc[m][3]);
            }
        }
    }
    float4 bias = ((const float4*)b1l)[cg];
#pragma unroll
    for (int m = 0; m < 8; m++) {
        int node = nodeBase + m;
        if (node < N_NODES) {
            float4 r;
            r.x = fmaxf(acc[m][0] + bias.x, 0.f);
            r.y = fmaxf(acc[m][1] + bias.y, 0.f);
            r.z = fmaxf(acc[m][2] + bias.z, 0.f);
            r.w = fmaxf(acc[m][3] + bias.w, 0.f);
            ((float4*)(g_h + (size_t)node * 64))[cg] = r;
        }
    }
}

// ---------------------------------------------------------------------------
// Kernel 6: GEMM2  p2h = (h @ W2l) as fp16 ; out = h @ W2r + b2l
// ---------------------------------------------------------------------------
__global__ __launch_bounds__(256) void gemm2_kernel(
    const float* __restrict__ W2l, const float* __restrict__ b2l,
    const float* __restrict__ W2r, float* __restrict__ out) {
    __shared__ float sB[64 * 64];
    int t  = threadIdx.x;
    int cg = t & 15;
    int ng = t >> 4;
    int nodeBase = blockIdx.x * 128 + ng * 8;

    float acc[8][4];
#pragma unroll
    for (int m = 0; m < 8; m++)
#pragma unroll
        for (int c = 0; c < 4; c++) acc[m][c] = 0.0f;

#pragma unroll
    for (int i = 0; i < 4; i++) {
        int f4 = t + i * 256;
        int k  = f4 >> 4;
        int jq = f4 & 15;
        float4 v = (jq < 8) ? ((const float4*)W2l)[k * 8 + jq]
                            : ((const float4*)W2r)[k * 8 + (jq - 8)];
        ((float4*)sB)[f4] = v;
    }
    __syncthreads();
    const float4* A4  = (const float4*)g_h;
    const float4* sB4 = (const float4*)sB;
#pragma unroll 4
    for (int k4 = 0; k4 < 16; k4++) {
        float4 b0 = sB4[(k4 * 4 + 0) * 16 + cg];
        float4 b1 = sB4[(k4 * 4 + 1) * 16 + cg];
        float4 b2 = sB4[(k4 * 4 + 2) * 16 + cg];
        float4 b3 = sB4[(k4 * 4 + 3) * 16 + cg];
#pragma unroll
        for (int m = 0; m < 8; m++) {
            int node = min(nodeBase + m, N_NODES - 1);
            float4 a = A4[(size_t)node * 16 + k4];
            acc[m][0] = fmaf(a.x, b0.x, acc[m][0]);
            acc[m][1] = fmaf(a.x, b0.y, acc[m][1]);
            acc[m][2] = fmaf(a.x, b0.z, acc[m][2]);
            acc[m][3] = fmaf(a.x, b0.w, acc[m][3]);
            acc[m][0] = fmaf(a.y, b1.x, acc[m][0]);
            acc[m][1] = fmaf(a.y, b1.y, acc[m][1]);
            acc[m][2] = fmaf(a.y, b1.z, acc[m][2]);
            acc[m][3] = fmaf(a.y, b1.w, acc[m][3]);
            acc[m][0] = fmaf(a.z, b2.x, acc[m][0]);
            acc[m][1] = fmaf(a.z, b2.y, acc[m][1]);
            acc[m][2] = fmaf(a.z, b2.z, acc[m][2]);
            acc[m][3] = fmaf(a.z, b2.w, acc[m][3]);
            acc[m][0] = fmaf(a.w, b3.x, acc[m][0]);
            acc[m][1] = fmaf(a.w, b3.y, acc[m][1]);
            acc[m][2] = fmaf(a.w, b3.z, acc[m][2]);
            acc[m][3] = fmaf(a.w, b3.w, acc[m][3]);
        }
    }
#pragma unroll
    for (int m = 0; m < 8; m++) {
        int node = nodeBase + m;
        if (node < N_NODES) {
            if (cg < 8) {   // p2 -> fp16 (one 8B store of 4 half)
                __half2 h0 = __floats2half2_rn(acc[m][0], acc[m][1]);
                __half2 h1 = __floats2half2_rn(acc[m][2], acc[m][3]);
                uint2 packed = make_uint2(h2_bits(h0), h2_bits(h1));
                ((uint2*)(g_p2h + (size_t)node * 32))[cg] = packed;
            } else {        // out = h @ W2r + b2l
                float4 bias = ((const float4*)b2l)[cg - 8];
                float4 r;
                r.x = acc[m][0] + bias.x;
                r.y = acc[m][1] + bias.y;
                r.z = acc[m][2] + bias.z;
                r.w = acc[m][3] + bias.w;
                ((float4*)(out + (size_t)node * 32))[cg - 8] = r;
            }
        }
    }
}

// ---------------------------------------------------------------------------
// Kernel 7: agg2 + final — one warp per dst node. out += mean of p2h[src].
// 32-bit address arithmetic.
// ---------------------------------------------------------------------------
__global__ __launch_bounds__(256) void agg2_kernel(float* __restrict__ out) {
    int warp = (blockIdx.x * blockDim.x + threadIdx.x) >> 5;
    if (warp >= N_NODES) return;
    unsigned lane = threadIdx.x & 31;
    int row = g_rowstart[warp];
    int n   = g_rowstart[warp + 1] - row;
    const int* cs = g_csr + row;
    float a0 = 0.f, a1 = 0.f, a2 = 0.f, a3 = 0.f;
    int k = 0;
    for (; k + 8 <= n; k += 8) {
        unsigned o0 = (unsigned)cs[k + 0] * 32u + lane;
        unsigned o1 = (unsigned)cs[k + 1] * 32u + lane;
        unsigned o2 = (unsigned)cs[k + 2] * 32u + lane;
        unsigned o3 = (unsigned)cs[k + 3] * 32u + lane;
        unsigned o4 = (unsigned)cs[k + 4] * 32u + lane;
        unsigned o5 = (unsigned)cs[k + 5] * 32u + lane;
        unsigned o6 = (unsigned)cs[k + 6] * 32u + lane;
        unsigned o7 = (unsigned)cs[k + 7] * 32u + lane;
        float v0 = __half2float(g_p2h[o0]);
        float v1 = __half2float(g_p2h[o1]);
        float v2 = __half2float(g_p2h[o2]);
        float v3 = __half2float(g_p2h[o3]);
        float v4 = __half2float(g_p2h[o4]);
        float v5 = __half2float(g_p2h[o5]);
        float v6 = __half2float(g_p2h[o6]);
        float v7 = __half2float(g_p2h[o7]);
        a0 += v0 + v1; a1 += v2 + v3; a2 += v4 + v5; a3 += v6 + v7;
    }
    for (; k < n; k++) a0 += __half2float(g_p2h[(unsigned)cs[k] * 32u + lane]);
    float invd = 1.0f / (float)max(n, 1);
    float total = (a0 + a1) + (a2 + a3);
    unsigned oi = (unsigned)warp * 32u + lane;
    out[oi] = fmaf(total, invd, out[oi]);
}

extern "C" void kernel_launch(void* const* d_in, const int* in_sizes, int n_in,
                              void* d_out, int out_size) {
    const float* x   = (const float*)d_in[0];
    const int*   ei  = (const int*)d_in[1];   // int32
    const float* W1l = (const float*)d_in[2];
    const float* b1l = (const float*)d_in[3];
    const float* W1r = (const float*)d_in[4];
    const float* W2l = (const float*)d_in[5];
    const float* b2l = (const float*)d_in[6];
    const float* W2r = (const float*)d_in[7];
    float* out = (float*)d_out;
    int E = in_sizes[1] / 2;

    void* p_degi;
    cudaGetSymbolAddress(&p_degi, g_degi);
    cudaMemsetAsync(p_degi, 0, (size_t)N_NODES * sizeof(int), 0);

    {   // kernel 1: hist + rank + x->fp16
        int tE = (E + 3) / 4;
        int tX = (N_NODES * IN_C + 7) / 8;
        int threads = tE > tX ? tE : tX;
        hist_xconv_kernel<<<(threads + 255) / 256, 256>>>(ei, x, E);
    }
    scan_kernel<<<1, 1024>>>();                       // kernel 2
    {
        int threads = (E + 3) / 4;                    // kernel 3 (atomic-free)
        fill_kernel<<<(threads + 255) / 256, 256>>>(ei, E);
    }
    {   // kernel 4 (profiled): agg1
        unsigned total = (unsigned)N_NODES * 32u;
        agg1_kernel<<<(total + 255) / 256, 256>>>();
    }
    {
        int blocks = (N_NODES + 127) / 128;           // kernel 5
        gemm1_kernel<<<blocks, 256>>>(x, W1l, b1l, W1r);
    }
    {
        int blocks = (N_NODES + 127) / 128;           // kernel 6
        gemm2_kernel<<<blocks, 256>>>(W2l, b2l, W2r, out);
    }
    {   // kernel 7: agg2 + final add
        unsigned total = (unsigned)N_NODES * 32u;
        agg2_kernel<<<(total + 255) / 256, 256>>>(out);
    }
}

// round 8
// speedup vs baseline: 1.2279x; 1.0055x over previous
#include <cuda_runtime.h>
#include <cuda_fp16.h>
#include <cstdint>

#define N_NODES 100000
#define N_EDGES_MAX 3200000
#define IN_C 64
#define HID_C 64
#define OUT_C 32

// Scratch (static __device__ arrays per harness rules)
__device__ __align__(16) float  g_sum1[(size_t)N_NODES * HID_C];  // mean-agg L1
__device__ __align__(16) float  g_h   [(size_t)N_NODES * HID_C];
__device__ __align__(16) float  g_pre [(size_t)N_NODES * HID_C];  // x@W1r + b1l
__device__ __align__(16) __half g_xh  [(size_t)N_NODES * IN_C];   // x in fp16
__device__ __align__(16) __half g_p2h [(size_t)N_NODES * OUT_C];  // h@W2l fp16
__device__ __align__(16) int    g_csr [N_EDGES_MAX];
__device__ __align__(16) int    g_rank[N_EDGES_MAX];
__device__ __align__(16) int    g_degi[N_NODES];
__device__ __align__(16) int    g_rowstart[N_NODES + 1];

static __device__ __forceinline__ unsigned h2_bits(__half2 h) {
    return *reinterpret_cast<const unsigned*>(&h);
}
static __device__ __forceinline__ float2 u32_to_f2(unsigned u) {
    return __half22float2(*reinterpret_cast<const __half2*>(&u));
}

// ---------------------------------------------------------------------------
// Kernel: degree histogram + per-edge rank (atomic return) + x -> fp16.
// ---------------------------------------------------------------------------
__global__ void hist_xconv_kernel(const int* __restrict__ ei,
                                  const float* __restrict__ x, int E) {
    int t = blockIdx.x * blockDim.x + threadIdx.x;
    int e0 = t * 4;
    int d[4];
#pragma unroll
    for (int j = 0; j < 4; j++) {
        int e = e0 + j;
        if (e < E) d[j] = ei[(size_t)E + e];
    }
    int r[4];
#pragma unroll
    for (int j = 0; j < 4; j++) {
        int e = e0 + j;
        if (e < E) r[j] = atomicAdd(&g_degi[d[j]], 1);
    }
#pragma unroll
    for (int j = 0; j < 4; j++) {
        int e = e0 + j;
        if (e < E) g_rank[e] = r[j];
    }
    size_t xi = (size_t)t * 8;
    if (xi + 8 <= (size_t)N_NODES * IN_C) {
        float4 f0 = ((const float4*)x)[t * 2];
        float4 f1 = ((const float4*)x)[t * 2 + 1];
        __half2 h0 = __floats2half2_rn(f0.x, f0.y);
        __half2 h1 = __floats2half2_rn(f0.z, f0.w);
        __half2 h2 = __floats2half2_rn(f1.x, f1.y);
        __half2 h3 = __floats2half2_rn(f1.z, f1.w);
        uint4 packed = make_uint4(h2_bits(h0), h2_bits(h1), h2_bits(h2), h2_bits(h3));
        ((uint4*)g_xh)[t] = packed;
    }
}

// ---------------------------------------------------------------------------
// Kernel: single-block exclusive scan of degrees -> rowstart.
// ---------------------------------------------------------------------------
__global__ __launch_bounds__(1024) void scan_kernel() {
    __shared__ int ssum[1024];
    int t = threadIdx.x;
    const int CH = (N_NODES + 1023) / 1024;
    int start = t * CH;
    int endi  = min(start + CH, N_NODES);
    int s0 = 0, s1 = 0, s2 = 0, s3 = 0;
    int i = start;
    for (; i + 4 <= endi; i += 4) {
        s0 += g_degi[i];
        s1 += g_degi[i + 1];
        s2 += g_degi[i + 2];
        s3 += g_degi[i + 3];
    }
    for (; i < endi; i++) s0 += g_degi[i];
    ssum[t] = (s0 + s1) + (s2 + s3);
    __syncthreads();
    for (int off = 1; off < 1024; off <<= 1) {
        int v = (t >= off) ? ssum[t - off] : 0;
        __syncthreads();
        ssum[t] += v;
        __syncthreads();
    }
    int prefix = (t == 0) ? 0 : ssum[t - 1];
    for (int k = start; k < endi; k++) {
        g_rowstart[k] = prefix;
        prefix += g_degi[k];
    }
    if (t == 1023) g_rowstart[N_NODES] = ssum[1023];
}

// ---------------------------------------------------------------------------
// Kernel: fill CSR — no atomics (pos = rowstart[dst] + rank[e]).
// ---------------------------------------------------------------------------
__global__ void fill_kernel(const int* __restrict__ ei, int E) {
    int e0 = (blockIdx.x * blockDim.x + threadIdx.x) * 4;
    int s[4], d[4], r[4];
#pragma unroll
    for (int j = 0; j < 4; j++) {
        int e = e0 + j;
        if (e < E) {
            s[j] = ei[e];
            d[j] = ei[(size_t)E + e];
            r[j] = g_rank[e];
        }
    }
    int base[4];
#pragma unroll
    for (int j = 0; j < 4; j++) {
        int e = e0 + j;
        if (e < E) base[j] = g_rowstart[d[j]];
    }
#pragma unroll
    for (int j = 0; j < 4; j++) {
        int e = e0 + j;
        if (e < E) g_csr[base[j] + r[j]] = s[j];
    }
}

// ---------------------------------------------------------------------------
// Kernel: agg1 — one warp per dst node; 2 neighbors per round (half-warps).
// Lane covers 4 halves (8B) of one neighbor row (16 lanes x 8B = 128B row).
// ---------------------------------------------------------------------------
__global__ __launch_bounds__(256) void agg1_kernel() {
    int warp = (blockIdx.x * blockDim.x + threadIdx.x) >> 5;
    if (warp >= N_NODES) return;
    unsigned lane = threadIdx.x & 31;
    unsigned half = lane >> 4;      // 0 or 1: which neighbor of the pair
    unsigned l    = lane & 15;      // 8B chunk within row
    int row = g_rowstart[warp];
    int n   = g_rowstart[warp + 1] - row;
    const int* cs = g_csr + row;
    const uint2* xh2 = (const uint2*)g_xh;   // node row = 16 uint2
    float4 a0 = make_float4(0.f, 0.f, 0.f, 0.f);
    float4 a1 = a0, a2 = a0, a3 = a0;
    int k = 0;
    for (; k + 8 <= n; k += 8) {
        unsigned i0 = (unsigned)cs[k + 0 + half] * 16u + l;
        unsigned i1 = (unsigned)cs[k + 2 + half] * 16u + l;
        unsigned i2 = (unsigned)cs[k + 4 + half] * 16u + l;
        unsigned i3 = (unsigned)cs[k + 6 + half] * 16u + l;
        uint2 u0 = xh2[i0];
        uint2 u1 = xh2[i1];
        uint2 u2 = xh2[i2];
        uint2 u3 = xh2[i3];
        float2 f;
        f = u32_to_f2(u0.x); a0.x += f.x; a0.y += f.y;
        f = u32_to_f2(u0.y); a0.z += f.x; a0.w += f.y;
        f = u32_to_f2(u1.x); a1.x += f.x; a1.y += f.y;
        f = u32_to_f2(u1.y); a1.z += f.x; a1.w += f.y;
        f = u32_to_f2(u2.x); a2.x += f.x; a2.y += f.y;
        f = u32_to_f2(u2.y); a2.z += f.x; a2.w += f.y;
        f = u32_to_f2(u3.x); a3.x += f.x; a3.y += f.y;
        f = u32_to_f2(u3.y); a3.z += f.x; a3.w += f.y;
    }
    for (; k < n; k += 2) {
        int e = k + half;
        uint2 u = make_uint2(0u, 0u);
        if (e < n) u = xh2[(unsigned)cs[e] * 16u + l];
        float2 f;
        f = u32_to_f2(u.x); a0.x += f.x; a0.y += f.y;
        f = u32_to_f2(u.y); a0.z += f.x; a0.w += f.y;
    }
    float4 s;
    s.x = (a0.x + a1.x) + (a2.x + a3.x);
    s.y = (a0.y + a1.y) + (a2.y + a3.y);
    s.z = (a0.z + a1.z) + (a2.z + a3.z);
    s.w = (a0.w + a1.w) + (a2.w + a3.w);
    s.x += __shfl_xor_sync(0xffffffffu, s.x, 16);
    s.y += __shfl_xor_sync(0xffffffffu, s.y, 16);
    s.z += __shfl_xor_sync(0xffffffffu, s.z, 16);
    s.w += __shfl_xor_sync(0xffffffffu, s.w, 16);
    if (half == 0) {
        float invd = 1.0f / (float)max(n, 1);
        float4 r;
        r.x = s.x * invd; r.y = s.y * invd; r.z = s.z * invd; r.w = s.w * invd;
        ((float4*)g_sum1)[(unsigned)warp * 16u + l] = r;
    }
}

// ---------------------------------------------------------------------------
// Kernel: gemmR — pre = x @ W1r + b1l  (side stream; depends only on input)
// ---------------------------------------------------------------------------
__global__ __launch_bounds__(256) void gemmR_kernel(
    const float* __restrict__ x, const float* __restrict__ W1r,
    const float* __restrict__ b1l) {
    __shared__ float sB[64 * 64];
    int t  = threadIdx.x;
    int cg = t & 15;
    int ng = t >> 4;
    int nodeBase = blockIdx.x * 128 + ng * 8;

    float acc[8][4];
#pragma unroll
    for (int m = 0; m < 8; m++)
#pragma unroll
        for (int c = 0; c < 4; c++) acc[m][c] = 0.0f;

#pragma unroll
    for (int i = 0; i < 4; i++) {
        int f4 = t + i * 256;
        ((float4*)sB)[f4] = ((const float4*)W1r)[f4];
    }
    __syncthreads();
    const float4* A4  = (const float4*)x;
    const float4* sB4 = (const float4*)sB;
#pragma unroll 4
    for (int k4 = 0; k4 < 16; k4++) {
        float4 b0 = sB4[(k4 * 4 + 0) * 16 + cg];
        float4 b1 = sB4[(k4 * 4 + 1) * 16 + cg];
        float4 b2 = sB4[(k4 * 4 + 2) * 16 + cg];
        float4 b3 = sB4[(k4 * 4 + 3) * 16 + cg];
#pragma unroll
        for (int m = 0; m < 8; m++) {
            int node = min(nodeBase + m, N_NODES - 1);
            float4 a = A4[(size_t)node * 16 + k4];
            acc[m][0] = fmaf(a.x, b0.x, acc[m][0]);
            acc[m][1] = fmaf(a.x, b0.y, acc[m][1]);
            acc[m][2] = fmaf(a.x, b0.z, acc[m][2]);
            acc[m][3] = fmaf(a.x, b0.w, acc[m][3]);
            acc[m][0] = fmaf(a.y, b1.x, acc[m][0]);
            acc[m][1] = fmaf(a.y, b1.y, acc[m][1]);
            acc[m][2] = fmaf(a.y, b1.z, acc[m][2]);
            acc[m][3] = fmaf(a.y, b1.w, acc[m][3]);
            acc[m][0] = fmaf(a.z, b2.x, acc[m][0]);
            acc[m][1] = fmaf(a.z, b2.y, acc[m][1]);
            acc[m][2] = fmaf(a.z, b2.z, acc[m][2]);
            acc[m][3] = fmaf(a.z, b2.w, acc[m][3]);
            acc[m][0] = fmaf(a.w, b3.x, acc[m][0]);
            acc[m][1] = fmaf(a.w, b3.y, acc[m][1]);
            acc[m][2] = fmaf(a.w, b3.z, acc[m][2]);
            acc[m][3] = fmaf(a.w, b3.w, acc[m][3]);
        }
    }
    float4 bias = ((const float4*)b1l)[cg];
#pragma unroll
    for (int m = 0; m < 8; m++) {
        int node = nodeBase + m;
        if (node < N_NODES) {
            float4 r;
            r.x = acc[m][0] + bias.x;
            r.y = acc[m][1] + bias.y;
            r.z = acc[m][2] + bias.z;
            r.w = acc[m][3] + bias.w;
            ((float4*)(g_pre + (size_t)node * 64))[cg] = r;
        }
    }
}

// ---------------------------------------------------------------------------
// Kernel: gemm1 — h = relu( sum1 @ W1l + pre )
// ---------------------------------------------------------------------------
__global__ __launch_bounds__(256) void gemm1_kernel(const float* __restrict__ W1l) {
    __shared__ float sB[64 * 64];
    int t  = threadIdx.x;
    int cg = t & 15;
    int ng = t >> 4;
    int nodeBase = blockIdx.x * 128 + ng * 8;

    float acc[8][4];
#pragma unroll
    for (int m = 0; m < 8; m++)
#pragma unroll
        for (int c = 0; c < 4; c++) acc[m][c] = 0.0f;

#pragma unroll
    for (int i = 0; i < 4; i++) {
        int f4 = t + i * 256;
        ((float4*)sB)[f4] = ((const float4*)W1l)[f4];
    }
    __syncthreads();
    const float4* A4  = (const float4*)g_sum1;
    const float4* sB4 = (const float4*)sB;
#pragma unroll 4
    for (int k4 = 0; k4 < 16; k4++) {
        float4 b0 = sB4[(k4 * 4 + 0) * 16 + cg];
        float4 b1 = sB4[(k4 * 4 + 1) * 16 + cg];
        float4 b2 = sB4[(k4 * 4 + 2) * 16 + cg];
        float4 b3 = sB4[(k4 * 4 + 3) * 16 + cg];
#pragma unroll
        for (int m = 0; m < 8; m++) {
            int node = min(nodeBase + m, N_NODES - 1);
            float4 a = A4[(size_t)node * 16 + k4];
            acc[m][0] = fmaf(a.x, b0.x, acc[m][0]);
            acc[m][1] = fmaf(a.x, b0.y, acc[m][1]);
            acc[m][2] = fmaf(a.x, b0.z, acc[m][2]);
            acc[m][3] = fmaf(a.x, b0.w, acc[m][3]);
            acc[m][0] = fmaf(a.y, b1.x, acc[m][0]);
            acc[m][1] = fmaf(a.y, b1.y, acc[m][1]);
            acc[m][2] = fmaf(a.y, b1.z, acc[m][2]);
            acc[m][3] = fmaf(a.y, b1.w, acc[m][3]);
            acc[m][0] = fmaf(a.z, b2.x, acc[m][0]);
            acc[m][1] = fmaf(a.z, b2.y, acc[m][1]);
            acc[m][2] = fmaf(a.z, b2.z, acc[m][2]);
            acc[m][3] = fmaf(a.z, b2.w, acc[m][3]);
            acc[m][0] = fmaf(a.w, b3.x, acc[m][0]);
            acc[m][1] = fmaf(a.w, b3.y, acc[m][1]);
            acc[m][2] = fmaf(a.w, b3.z, acc[m][2]);
            acc[m][3] = fmaf(a.w, b3.w, acc[m][3]);
        }
    }
#pragma unroll
    for (int m = 0; m < 8; m++) {
        int node = nodeBase + m;
        if (node < N_NODES) {
            float4 p = ((const float4*)(g_pre + (size_t)node * 64))[cg];
            float4 r;
            r.x = fmaxf(acc[m][0] + p.x, 0.f);
            r.y = fmaxf(acc[m][1] + p.y, 0.f);
            r.z = fmaxf(acc[m][2] + p.z, 0.f);
            r.w = fmaxf(acc[m][3] + p.w, 0.f);
            ((float4*)(g_h + (size_t)node * 64))[cg] = r;
        }
    }
}

// ---------------------------------------------------------------------------
// Kernel: gemm2 — p2h = (h @ W2l) fp16 ; out = h @ W2r + b2l
// ---------------------------------------------------------------------------
__global__ __launch_bounds__(256) void gemm2_kernel(
    const float* __restrict__ W2l, const float* __restrict__ b2l,
    const float* __restrict__ W2r, float* __restrict__ out) {
    __shared__ float sB[64 * 64];
    int t  = threadIdx.x;
    int cg = t & 15;
    int ng = t >> 4;
    int nodeBase = blockIdx.x * 128 + ng * 8;

    float acc[8][4];
#pragma unroll
    for (int m = 0; m < 8; m++)
#pragma unroll
        for (int c = 0; c < 4; c++) acc[m][c] = 0.0f;

#pragma unroll
    for (int i = 0; i < 4; i++) {
        int f4 = t + i * 256;
        int k  = f4 >> 4;
        int jq = f4 & 15;
        float4 v = (jq < 8) ? ((const float4*)W2l)[k * 8 + jq]
                            : ((const float4*)W2r)[k * 8 + (jq - 8)];
        ((float4*)sB)[f4] = v;
    }
    __syncthreads();
    const float4* A4  = (const float4*)g_h;
    const float4* sB4 = (const float4*)sB;
#pragma unroll 4
    for (int k4 = 0; k4 < 16; k4++) {
        float4 b0 = sB4[(k4 * 4 + 0) * 16 + cg];
        float4 b1 = sB4[(k4 * 4 + 1) * 16 + cg];
        float4 b2 = sB4[(k4 * 4 + 2) * 16 + cg];
        float4 b3 = sB4[(k4 * 4 + 3) * 16 + cg];
#pragma unroll
        for (int m = 0; m < 8; m++) {
            int node = min(nodeBase + m, N_NODES - 1);
            float4 a = A4[(size_t)node * 16 + k4];
            acc[m][0] = fmaf(a.x, b0.x, acc[m][0]);
            acc[m][1] = fmaf(a.x, b0.y, acc[m][1]);
            acc[m][2] = fmaf(a.x, b0.z, acc[m][2]);
            acc[m][3] = fmaf(a.x, b0.w, acc[m][3]);
            acc[m][0] = fmaf(a.y, b1.x, acc[m][0]);
            acc[m][1] = fmaf(a.y, b1.y, acc[m][1]);
            acc[m][2] = fmaf(a.y, b1.z, acc[m][2]);
            acc[m][3] = fmaf(a.y, b1.w, acc[m][3]);
            acc[m][0] = fmaf(a.z, b2.x, acc[m][0]);
            acc[m][1] = fmaf(a.z, b2.y, acc[m][1]);
            acc[m][2] = fmaf(a.z, b2.z, acc[m][2]);
            acc[m][3] = fmaf(a.z, b2.w, acc[m][3]);
            acc[m][0] = fmaf(a.w, b3.x, acc[m][0]);
            acc[m][1] = fmaf(a.w, b3.y, acc[m][1]);
            acc[m][2] = fmaf(a.w, b3.z, acc[m][2]);
            acc[m][3] = fmaf(a.w, b3.w, acc[m][3]);
        }
    }
#pragma unroll
    for (int m = 0; m < 8; m++) {
        int node = nodeBase + m;
        if (node < N_NODES) {
            if (cg < 8) {
                __half2 h0 = __floats2half2_rn(acc[m][0], acc[m][1]);
                __half2 h1 = __floats2half2_rn(acc[m][2], acc[m][3]);
                uint2 packed = make_uint2(h2_bits(h0), h2_bits(h1));
                ((uint2*)(g_p2h + (size_t)node * 32))[cg] = packed;
            } else {
                float4 bias = ((const float4*)b2l)[cg - 8];
                float4 r;
                r.x = acc[m][0] + bias.x;
                r.y = acc[m][1] + bias.y;
                r.z = acc[m][2] + bias.z;
                r.w = acc[m][3] + bias.w;
                ((float4*)(out + (size_t)node * 32))[cg - 8] = r;
            }
        }
    }
}

// ---------------------------------------------------------------------------
// Kernel: agg2 + final — one warp per node; 4 neighbors per round
// (quarter-warps: 8 lanes x 8B = 64B row). out += mean(p2h[src]).
// ---------------------------------------------------------------------------
__global__ __launch_bounds__(256) void agg2_kernel(float* __restrict__ out) {
    int warp = (blockIdx.x * blockDim.x + threadIdx.x) >> 5;
    if (warp >= N_NODES) return;
    unsigned lane = threadIdx.x & 31;
    unsigned g    = lane >> 3;      // 0..3: which neighbor of the quad
    unsigned l    = lane & 7;       // 8B chunk within row
    int row = g_rowstart[warp];
    int n   = g_rowstart[warp + 1] - row;
    const int* cs = g_csr + row;
    const uint2* p2 = (const uint2*)g_p2h;   // node row = 8 uint2
    float4 a0 = make_float4(0.f, 0.f, 0.f, 0.f);
    float4 a1 = a0, a2 = a0, a3 = a0;
    int k = 0;
    for (; k + 16 <= n; k += 16) {
        unsigned i0 = (unsigned)cs[k + 0  + g] * 8u + l;
        unsigned i1 = (unsigned)cs[k + 4  + g] * 8u + l;
        unsigned i2 = (unsigned)cs[k + 8  + g] * 8u + l;
        unsigned i3 = (unsigned)cs[k + 12 + g] * 8u + l;
        uint2 u0 = p2[i0];
        uint2 u1 = p2[i1];
        uint2 u2 = p2[i2];
        uint2 u3 = p2[i3];
        float2 f;
        f = u32_to_f2(u0.x); a0.x += f.x; a0.y += f.y;
        f = u32_to_f2(u0.y); a0.z += f.x; a0.w += f.y;
        f = u32_to_f2(u1.x); a1.x += f.x; a1.y += f.y;
        f = u32_to_f2(u1.y); a1.z += f.x; a1.w += f.y;
        f = u32_to_f2(u2.x); a2.x += f.x; a2.y += f.y;
        f = u32_to_f2(u2.y); a2.z += f.x; a2.w += f.y;
        f = u32_to_f2(u3.x); a3.x += f.x; a3.y += f.y;
        f = u32_to_f2(u3.y); a3.z += f.x; a3.w += f.y;
    }
    for (; k < n; k += 4) {
        int e = k + g;
        uint2 u = make_uint2(0u, 0u);
        if (e < n) u = p2[(unsigned)cs[e] * 8u + l];
        float2 f;
        f = u32_to_f2(u.x); a0.x += f.x; a0.y += f.y;
        f = u32_to_f2(u.y); a0.z += f.x; a0.w += f.y;
    }
    float4 s;
    s.x = (a0.x + a1.x) + (a2.x + a3.x);
    s.y = (a0.y + a1.y) + (a2.y + a3.y);
    s.z = (a0.z + a1.z) + (a2.z + a3.z);
    s.w = (a0.w + a1.w) + (a2.w + a3.w);
#pragma unroll
    for (int off = 8; off <= 16; off <<= 1) {
        s.x += __shfl_xor_sync(0xffffffffu, s.x, off);
        s.y += __shfl_xor_sync(0xffffffffu, s.y, off);
        s.z += __shfl_xor_sync(0xffffffffu, s.z, off);
        s.w += __shfl_xor_sync(0xffffffffu, s.w, off);
    }
    if (lane < 8) {
        float invd = 1.0f / (float)max(n, 1);
        unsigned oi = (unsigned)warp * 8u + l;
        float4 o = ((float4*)out)[oi];
        o.x = fmaf(s.x, invd, o.x);
        o.y = fmaf(s.y, invd, o.y);
        o.z = fmaf(s.z, invd, o.z);
        o.w = fmaf(s.w, invd, o.w);
        ((float4*)out)[oi] = o;
    }
}

extern "C" void kernel_launch(void* const* d_in, const int* in_sizes, int n_in,
                              void* d_out, int out_size) {
    const float* x   = (const float*)d_in[0];
    const int*   ei  = (const int*)d_in[1];   // int32
    const float* W1l = (const float*)d_in[2];
    const float* b1l = (const float*)d_in[3];
    const float* W1r = (const float*)d_in[4];
    const float* W2l = (const float*)d_in[5];
    const float* b2l = (const float*)d_in[6];
    const float* W2r = (const float*)d_in[7];
    float* out = (float*)d_out;
    int E = in_sizes[1] / 2;

    // Lazily-created side stream + events (host objects only; created on the
    // first, non-captured call; identical launch work on every call).
    static cudaStream_t s_side = nullptr;
    static cudaEvent_t  ev_fork = nullptr, ev_join = nullptr;
    if (s_side == nullptr) {
        cudaStreamCreateWithFlags(&s_side, cudaStreamNonBlocking);
        cudaEventCreateWithFlags(&ev_fork, cudaEventDisableTiming);
        cudaEventCreateWithFlags(&ev_join, cudaEventDisableTiming);
    }

    void* p_degi;
    cudaGetSymbolAddress(&p_degi, g_degi);
    cudaMemsetAsync(p_degi, 0, (size_t)N_NODES * sizeof(int), 0);

    int gemmBlocks = (N_NODES + 127) / 128;

    // Fork: pre = x@W1r + b1l on side stream (independent of CSR build)
    cudaEventRecord(ev_fork, 0);
    cudaStreamWaitEvent(s_side, ev_fork, 0);
    gemmR_kernel<<<gemmBlocks, 256, 0, s_side>>>(x, W1r, b1l);
    cudaEventRecord(ev_join, s_side);

    {   // hist + rank + x->fp16
        int tE = (E + 3) / 4;
        int tX = (N_NODES * IN_C + 7) / 8;
        int threads = tE > tX ? tE : tX;
        hist_xconv_kernel<<<(threads + 255) / 256, 256>>>(ei, x, E);
    }
    scan_kernel<<<1, 1024>>>();
    {
        int threads = (E + 3) / 4;
        fill_kernel<<<(threads + 255) / 256, 256>>>(ei, E);
    }
    {   // agg1
        unsigned total = (unsigned)N_NODES * 32u;
        agg1_kernel<<<(total + 255) / 256, 256>>>();
    }
    // Join side stream before gemm1 (needs g_pre)
    cudaStreamWaitEvent(0, ev_join, 0);
    gemm1_kernel<<<gemmBlocks, 256>>>(W1l);
    gemm2_kernel<<<gemmBlocks, 256>>>(W2l, b2l, W2r, out);
    {   // agg2 + final add
        unsigned total = (unsigned)N_NODES * 32u;
        agg2_kernel<<<(total + 255) / 256, 256>>>(out);
    }
}

// round 9
// speedup vs baseline: 1.5832x; 1.2893x over previous
#include <cuda_runtime.h>
#include <cuda_fp16.h>
#include <cstdint>

#define N_NODES 100000
#define N_EDGES_MAX 3200000
#define IN_C 64
#define HID_C 64
#define OUT_C 32
#define SCAN_BLOCKS 98   // 98 * 1024 >= N_NODES

// Scratch (static __device__ arrays per harness rules)
__device__ __align__(16) float  g_sum1[(size_t)N_NODES * HID_C];  // mean-agg L1
__device__ __align__(16) float  g_h   [(size_t)N_NODES * HID_C];
__device__ __align__(16) float  g_pre [(size_t)N_NODES * HID_C];  // x@W1r + b1l
__device__ __align__(16) __half g_xh  [(size_t)N_NODES * IN_C];   // x in fp16
__device__ __align__(16) __half g_p2h [(size_t)N_NODES * OUT_C];  // h@W2l fp16
__device__ __align__(16) int    g_csr [N_EDGES_MAX];
__device__ __align__(16) int    g_rank[N_EDGES_MAX];
__device__ __align__(16) int    g_degi[N_NODES];
__device__ __align__(16) int    g_rowstart[N_NODES + 1];
__device__ __align__(16) int    g_local[N_NODES];
__device__ __align__(16) int    g_bsum[SCAN_BLOCKS];
__device__ __align__(16) int    g_boff[SCAN_BLOCKS];

static __device__ __forceinline__ unsigned h2_bits(__half2 h) {
    return *reinterpret_cast<const unsigned*>(&h);
}
static __device__ __forceinline__ float2 u32_to_f2(unsigned u) {
    return __half22float2(*reinterpret_cast<const __half2*>(&u));
}
// --- packed f32x2 helpers (FFMA2 path; PTX-only per B300 SASS notes) ---
static __device__ __forceinline__ unsigned long long dup2(float v) {
    unsigned long long r;
    asm("mov.b64 %0, {%1, %1};" : "=l"(r) : "f"(v));
    return r;
}
static __device__ __forceinline__ unsigned long long fma2(
    unsigned long long a, unsigned long long b, unsigned long long c) {
    unsigned long long d;
    asm("fma.rn.f32x2 %0, %1, %2, %3;" : "=l"(d) : "l"(a), "l"(b), "l"(c));
    return d;
}
static __device__ __forceinline__ void unpack2(unsigned long long v,
                                               float& lo, float& hi) {
    asm("mov.b64 {%0, %1}, %2;" : "=f"(lo), "=f"(hi) : "l"(v));
}

// ---------------------------------------------------------------------------
// Kernel: degree histogram + per-edge rank (atomic return) + x -> fp16.
// ---------------------------------------------------------------------------
__global__ void hist_xconv_kernel(const int* __restrict__ ei,
                                  const float* __restrict__ x, int E) {
    int t = blockIdx.x * blockDim.x + threadIdx.x;
    int e0 = t * 4;
    int d[4];
#pragma unroll
    for (int j = 0; j < 4; j++) {
        int e = e0 + j;
        if (e < E) d[j] = ei[(size_t)E + e];
    }
    int r[4];
#pragma unroll
    for (int j = 0; j < 4; j++) {
        int e = e0 + j;
        if (e < E) r[j] = atomicAdd(&g_degi[d[j]], 1);
    }
#pragma unroll
    for (int j = 0; j < 4; j++) {
        int e = e0 + j;
        if (e < E) g_rank[e] = r[j];
    }
    size_t xi = (size_t)t * 8;
    if (xi + 8 <= (size_t)N_NODES * IN_C) {
        float4 f0 = ((const float4*)x)[t * 2];
        float4 f1 = ((const float4*)x)[t * 2 + 1];
        __half2 h0 = __floats2half2_rn(f0.x, f0.y);
        __half2 h1 = __floats2half2_rn(f0.z, f0.w);
        __half2 h2 = __floats2half2_rn(f1.x, f1.y);
        __half2 h3 = __floats2half2_rn(f1.z, f1.w);
        uint4 packed = make_uint4(h2_bits(h0), h2_bits(h1), h2_bits(h2), h2_bits(h3));
        ((uint4*)g_xh)[t] = packed;
    }
}

// ---------------------------------------------------------------------------
// Parallel scan, 3 kernels.
// ---------------------------------------------------------------------------
__global__ __launch_bounds__(1024) void scanA_kernel() {
    __shared__ int ssum[1024];
    int t = threadIdx.x;
    int node = blockIdx.x * 1024 + t;
    int v = (node < N_NODES) ? g_degi[node] : 0;
    ssum[t] = v;
    __syncthreads();
    for (int off = 1; off < 1024; off <<= 1) {
        int u = (t >= off) ? ssum[t - off] : 0;
        __syncthreads();
        ssum[t] += u;
        __syncthreads();
    }
    int incl = ssum[t];
    if (node < N_NODES) g_local[node] = incl - v;
    if (t == 1023) g_bsum[blockIdx.x] = incl;
}

__global__ __launch_bounds__(128) void scanB_kernel() {
    __shared__ int ssum[128];
    int t = threadIdx.x;
    int v = (t < SCAN_BLOCKS) ? g_bsum[t] : 0;
    ssum[t] = v;
    __syncthreads();
    for (int off = 1; off < 128; off <<= 1) {
        int u = (t >= off) ? ssum[t - off] : 0;
        __syncthreads();
        ssum[t] += u;
        __syncthreads();
    }
    if (t < SCAN_BLOCKS) g_boff[t] = ssum[t] - v;
    if (t == SCAN_BLOCKS - 1) g_rowstart[N_NODES] = ssum[t];
}

__global__ __launch_bounds__(1024) void scanC_kernel() {
    int node = blockIdx.x * 1024 + threadIdx.x;
    if (node < N_NODES)
        g_rowstart[node] = g_local[node] + g_boff[blockIdx.x];
}

// ---------------------------------------------------------------------------
// Kernel: fill CSR — no atomics (pos = rowstart[dst] + rank[e]).
// ---------------------------------------------------------------------------
__global__ void fill_kernel(const int* __restrict__ ei, int E) {
    int e0 = (blockIdx.x * blockDim.x + threadIdx.x) * 4;
    int s[4], d[4], r[4];
#pragma unroll
    for (int j = 0; j < 4; j++) {
        int e = e0 + j;
        if (e < E) {
            s[j] = ei[e];
            d[j] = ei[(size_t)E + e];
            r[j] = g_rank[e];
        }
    }
    int base[4];
#pragma unroll
    for (int j = 0; j < 4; j++) {
        int e = e0 + j;
        if (e < E) base[j] = g_rowstart[d[j]];
    }
#pragma unroll
    for (int j = 0; j < 4; j++) {
        int e = e0 + j;
        if (e < E) g_csr[base[j] + r[j]] = s[j];
    }
}

// ---------------------------------------------------------------------------
// Kernel: agg1 — one warp per dst node; 2 neighbors per round (half-warps).
// ---------------------------------------------------------------------------
__global__ __launch_bounds__(256) void agg1_kernel() {
    int warp = (blockIdx.x * blockDim.x + threadIdx.x) >> 5;
    if (warp >= N_NODES) return;
    unsigned lane = threadIdx.x & 31;
    unsigned half = lane >> 4;
    unsigned l    = lane & 15;
    int row = g_rowstart[warp];
    int n   = g_rowstart[warp + 1] - row;
    const int* cs = g_csr + row;
    const uint2* xh2 = (const uint2*)g_xh;
    float4 a0 = make_float4(0.f, 0.f, 0.f, 0.f);
    float4 a1 = a0, a2 = a0, a3 = a0;
    int k = 0;
    for (; k + 8 <= n; k += 8) {
        unsigned i0 = (unsigned)cs[k + 0 + half] * 16u + l;
        unsigned i1 = (unsigned)cs[k + 2 + half] * 16u + l;
        unsigned i2 = (unsigned)cs[k + 4 + half] * 16u + l;
        unsigned i3 = (unsigned)cs[k + 6 + half] * 16u + l;
        uint2 u0 = xh2[i0];
        uint2 u1 = xh2[i1];
        uint2 u2 = xh2[i2];
        uint2 u3 = xh2[i3];
        float2 f;
        f = u32_to_f2(u0.x); a0.x += f.x; a0.y += f.y;
        f = u32_to_f2(u0.y); a0.z += f.x; a0.w += f.y;
        f = u32_to_f2(u1.x); a1.x += f.x; a1.y += f.y;
        f = u32_to_f2(u1.y); a1.z += f.x; a1.w += f.y;
        f = u32_to_f2(u2.x); a2.x += f.x; a2.y += f.y;
        f = u32_to_f2(u2.y); a2.z += f.x; a2.w += f.y;
        f = u32_to_f2(u3.x); a3.x += f.x; a3.y += f.y;
        f = u32_to_f2(u3.y); a3.z += f.x; a3.w += f.y;
    }
    for (; k < n; k += 2) {
        int e = k + half;
        uint2 u = make_uint2(0u, 0u);
        if (e < n) u = xh2[(unsigned)cs[e] * 16u + l];
        float2 f;
        f = u32_to_f2(u.x); a0.x += f.x; a0.y += f.y;
        f = u32_to_f2(u.y); a0.z += f.x; a0.w += f.y;
    }
    float4 s;
    s.x = (a0.x + a1.x) + (a2.x + a3.x);
    s.y = (a0.y + a1.y) + (a2.y + a3.y);
    s.z = (a0.z + a1.z) + (a2.z + a3.z);
    s.w = (a0.w + a1.w) + (a2.w + a3.w);
    s.x += __shfl_xor_sync(0xffffffffu, s.x, 16);
    s.y += __shfl_xor_sync(0xffffffffu, s.y, 16);
    s.z += __shfl_xor_sync(0xffffffffu, s.z, 16);
    s.w += __shfl_xor_sync(0xffffffffu, s.w, 16);
    if (half == 0) {
        float invd = 1.0f / (float)max(n, 1);
        float4 r;
        r.x = s.x * invd; r.y = s.y * invd; r.z = s.z * invd; r.w = s.w * invd;
        ((float4*)g_sum1)[(unsigned)warp * 16u + l] = r;
    }
}

// ---------------------------------------------------------------------------
// Shared FFMA2 GEMM inner loop: acc(8 nodes x 4 cols) over K=64.
// A: row-major [node][16 float4], B staged in smem [k][64].
// ---------------------------------------------------------------------------
#define GEMM_CORE(A4, sB, accP, nodeBase, cg)                                 \
    {                                                                         \
        const ulonglong2* sBp = (const ulonglong2*)(sB);                      \
        _Pragma("unroll 4")                                                   \
        for (int k4 = 0; k4 < 16; k4++) {                                     \
            ulonglong2 b0 = sBp[(k4 * 4 + 0) * 16 + (cg)];                    \
            ulonglong2 b1 = sBp[(k4 * 4 + 1) * 16 + (cg)];                    \
            ulonglong2 b2 = sBp[(k4 * 4 + 2) * 16 + (cg)];                    \
            ulonglong2 b3 = sBp[(k4 * 4 + 3) * 16 + (cg)];                    \
            _Pragma("unroll")                                                 \
            for (int m = 0; m < 8; m++) {                                     \
                int node = min((nodeBase) + m, N_NODES - 1);                  \
                float4 a = (A4)[(size_t)node * 16 + k4];                      \
                unsigned long long ax = dup2(a.x), ay = dup2(a.y);            \
                unsigned long long az = dup2(a.z), aw = dup2(a.w);            \
                accP[m][0] = fma2(ax, b0.x, accP[m][0]);                      \
                accP[m][1] = fma2(ax, b0.y, accP[m][1]);                      \
                accP[m][0] = fma2(ay, b1.x, accP[m][0]);                      \
                accP[m][1] = fma2(ay, b1.y, accP[m][1]);                      \
                accP[m][0] = fma2(az, b2.x, accP[m][0]);                      \
                accP[m][1] = fma2(az, b2.y, accP[m][1]);                      \
                accP[m][0] = fma2(aw, b3.x, accP[m][0]);                      \
                accP[m][1] = fma2(aw, b3.y, accP[m][1]);                      \
            }                                                                 \
        }                                                                     \
    }

// ---------------------------------------------------------------------------
// Kernel: gemmR — pre = x @ W1r + b1l  (side stream)
// ---------------------------------------------------------------------------
__global__ __launch_bounds__(256) void gemmR_kernel(
    const float* __restrict__ x, const float* __restrict__ W1r,
    const float* __restrict__ b1l) {
    __shared__ float sB[64 * 64];
    int t  = threadIdx.x;
    int cg = t & 15;
    int ng = t >> 4;
    int nodeBase = blockIdx.x * 128 + ng * 8;

    unsigned long long accP[8][2];
#pragma unroll
    for (int m = 0; m < 8; m++) { accP[m][0] = 0ull; accP[m][1] = 0ull; }

#pragma unroll
    for (int i = 0; i < 4; i++) {
        int f4 = t + i * 256;
        ((float4*)sB)[f4] = ((const float4*)W1r)[f4];
    }
    __syncthreads();
    GEMM_CORE((const float4*)x, sB, accP, nodeBase, cg)
    float4 bias = ((const float4*)b1l)[cg];
#pragma unroll
    for (int m = 0; m < 8; m++) {
        int node = nodeBase + m;
        if (node < N_NODES) {
            float4 r;
            unpack2(accP[m][0], r.x, r.y);
            unpack2(accP[m][1], r.z, r.w);
            r.x += bias.x; r.y += bias.y; r.z += bias.z; r.w += bias.w;
            ((float4*)(g_pre + (size_t)node * 64))[cg] = r;
        }
    }
}

// ---------------------------------------------------------------------------
// Kernel: gemm1 — h = relu( sum1 @ W1l + pre )
// ---------------------------------------------------------------------------
__global__ __launch_bounds__(256) void gemm1_kernel(const float* __restrict__ W1l) {
    __shared__ float sB[64 * 64];
    int t  = threadIdx.x;
    int cg = t & 15;
    int ng = t >> 4;
    int nodeBase = blockIdx.x * 128 + ng * 8;

    unsigned long long accP[8][2];
#pragma unroll
    for (int m = 0; m < 8; m++) { accP[m][0] = 0ull; accP[m][1] = 0ull; }

#pragma unroll
    for (int i = 0; i < 4; i++) {
        int f4 = t + i * 256;
        ((float4*)sB)[f4] = ((const float4*)W1l)[f4];
    }
    __syncthreads();
    GEMM_CORE((const float4*)g_sum1, sB, accP, nodeBase, cg)
#pragma unroll
    for (int m = 0; m < 8; m++) {
        int node = nodeBase + m;
        if (node < N_NODES) {
            float4 p = ((const float4*)(g_pre + (size_t)node * 64))[cg];
            float4 r;
            unpack2(accP[m][0], r.x, r.y);
            unpack2(accP[m][1], r.z, r.w);
            r.x = fmaxf(r.x + p.x, 0.f);
            r.y = fmaxf(r.y + p.y, 0.f);
            r.z = fmaxf(r.z + p.z, 0.f);
            r.w = fmaxf(r.w + p.w, 0.f);
            ((float4*)(g_h + (size_t)node * 64))[cg] = r;
        }
    }
}

// ---------------------------------------------------------------------------
// Kernel: gemm2 — p2h = (h @ W2l) fp16 ; out = h @ W2r + b2l
// ---------------------------------------------------------------------------
__global__ __launch_bounds__(256) void gemm2_kernel(
    const float* __restrict__ W2l, const float* __restrict__ b2l,
    const float* __restrict__ W2r, float* __restrict__ out) {
    __shared__ float sB[64 * 64];
    int t  = threadIdx.x;
    int cg = t & 15;
    int ng = t >> 4;
    int nodeBase = blockIdx.x * 128 + ng * 8;

    unsigned long long accP[8][2];
#pragma unroll
    for (int m = 0; m < 8; m++) { accP[m][0] = 0ull; accP[m][1] = 0ull; }

#pragma unroll
    for (int i = 0; i < 4; i++) {
        int f4 = t + i * 256;
        int k  = f4 >> 4;
        int jq = f4 & 15;
        float4 v = (jq < 8) ? ((const float4*)W2l)[k * 8 + jq]
                            : ((const float4*)W2r)[k * 8 + (jq - 8)];
        ((float4*)sB)[f4] = v;
    }
    __syncthreads();
    GEMM_CORE((const float4*)g_h, sB, accP, nodeBase, cg)
#pragma unroll
    for (int m = 0; m < 8; m++) {
        int node = nodeBase + m;
        if (node < N_NODES) {
            float4 r;
            unpack2(accP[m][0], r.x, r.y);
            unpack2(accP[m][1], r.z, r.w);
            if (cg < 8) {
                __half2 h0 = __floats2half2_rn(r.x, r.y);
                __half2 h1 = __floats2half2_rn(r.z, r.w);
                uint2 packed = make_uint2(h2_bits(h0), h2_bits(h1));
                ((uint2*)(g_p2h + (size_t)node * 32))[cg] = packed;
            } else {
                float4 bias = ((const float4*)b2l)[cg - 8];
                r.x += bias.x; r.y += bias.y; r.z += bias.z; r.w += bias.w;
                ((float4*)(out + (size_t)node * 32))[cg - 8] = r;
            }
        }
    }
}

// ---------------------------------------------------------------------------
// Kernel: agg2 + final — one warp per node; 4 neighbors per round.
// ---------------------------------------------------------------------------
__global__ __launch_bounds__(256) void agg2_kernel(float* __restrict__ out) {
    int warp = (blockIdx.x * blockDim.x + threadIdx.x) >> 5;
    if (warp >= N_NODES) return;
    unsigned lane = threadIdx.x & 31;
    unsigned g    = lane >> 3;
    unsigned l    = lane & 7;
    int row = g_rowstart[warp];
    int n   = g_rowstart[warp + 1] - row;
    const int* cs = g_csr + row;
    const uint2* p2 = (const uint2*)g_p2h;
    float4 a0 = make_float4(0.f, 0.f, 0.f, 0.f);
    float4 a1 = a0, a2 = a0, a3 = a0;
    int k = 0;
    for (; k + 16 <= n; k += 16) {
        unsigned i0 = (unsigned)cs[k + 0  + g] * 8u + l;
        unsigned i1 = (unsigned)cs[k + 4  + g] * 8u + l;
        unsigned i2 = (unsigned)cs[k + 8  + g] * 8u + l;
        unsigned i3 = (unsigned)cs[k + 12 + g] * 8u + l;
        uint2 u0 = p2[i0];
        uint2 u1 = p2[i1];
        uint2 u2 = p2[i2];
        uint2 u3 = p2[i3];
        float2 f;
        f = u32_to_f2(u0.x); a0.x += f.x; a0.y += f.y;
        f = u32_to_f2(u0.y); a0.z += f.x; a0.w += f.y;
        f = u32_to_f2(u1.x); a1.x += f.x; a1.y += f.y;
        f = u32_to_f2(u1.y); a1.z += f.x; a1.w += f.y;
        f = u32_to_f2(u2.x); a2.x += f.x; a2.y += f.y;
        f = u32_to_f2(u2.y); a2.z += f.x; a2.w += f.y;
        f = u32_to_f2(u3.x); a3.x += f.x; a3.y += f.y;
        f = u32_to_f2(u3.y); a3.z += f.x; a3.w += f.y;
    }
    for (; k < n; k += 4) {
        int e = k + g;
        uint2 u = make_uint2(0u, 0u);
        if (e < n) u = p2[(unsigned)cs[e] * 8u + l];
        float2 f;
        f = u32_to_f2(u.x); a0.x += f.x; a0.y += f.y;
        f = u32_to_f2(u.y); a0.z += f.x; a0.w += f.y;
    }
    float4 s;
    s.x = (a0.x + a1.x) + (a2.x + a3.x);
    s.y = (a0.y + a1.y) + (a2.y + a3.y);
    s.z = (a0.z + a1.z) + (a2.z + a3.z);
    s.w = (a0.w + a1.w) + (a2.w + a3.w);
#pragma unroll
    for (int off = 8; off <= 16; off <<= 1) {
        s.x += __shfl_xor_sync(0xffffffffu, s.x, off);
        s.y += __shfl_xor_sync(0xffffffffu, s.y, off);
        s.z += __shfl_xor_sync(0xffffffffu, s.z, off);
        s.w += __shfl_xor_sync(0xffffffffu, s.w, off);
    }
    if (lane < 8) {
        float invd = 1.0f / (float)max(n, 1);
        unsigned oi = (unsigned)warp * 8u + l;
        float4 o = ((float4*)out)[oi];
        o.x = fmaf(s.x, invd, o.x);
        o.y = fmaf(s.y, invd, o.y);
        o.z = fmaf(s.z, invd, o.z);
        o.w = fmaf(s.w, invd, o.w);
        ((float4*)out)[oi] = o;
    }
}

extern "C" void kernel_launch(void* const* d_in, const int* in_sizes, int n_in,
                              void* d_out, int out_size) {
    const float* x   = (const float*)d_in[0];
    const int*   ei  = (const int*)d_in[1];   // int32
    const float* W1l = (const float*)d_in[2];
    const float* b1l = (const float*)d_in[3];
    const float* W1r = (const float*)d_in[4];
    const float* W2l = (const float*)d_in[5];
    const float* b2l = (const float*)d_in[6];
    const float* W2r = (const float*)d_in[7];
    float* out = (float*)d_out;
    int E = in_sizes[1] / 2;

    static cudaStream_t s_side = nullptr;
    static cudaEvent_t  ev_fork = nullptr, ev_join = nullptr;
    if (s_side == nullptr) {
        cudaStreamCreateWithFlags(&s_side, cudaStreamNonBlocking);
        cudaEventCreateWithFlags(&ev_fork, cudaEventDisableTiming);
        cudaEventCreateWithFlags(&ev_join, cudaEventDisableTiming);
    }

    void* p_degi;
    cudaGetSymbolAddress(&p_degi, g_degi);
    cudaMemsetAsync(p_degi, 0, (size_t)N_NODES * sizeof(int), 0);

    int gemmBlocks = (N_NODES + 127) / 128;

    // Fork: pre = x@W1r + b1l on side stream
    cudaEventRecord(ev_fork, 0);
    cudaStreamWaitEvent(s_side, ev_fork, 0);
    gemmR_kernel<<<gemmBlocks, 256, 0, s_side>>>(x, W1r, b1l);
    cudaEventRecord(ev_join, s_side);

    {   // hist + rank + x->fp16
        int tE = (E + 3) / 4;
        int tX = (N_NODES * IN_C + 7) / 8;
        int threads = tE > tX ? tE : tX;
        hist_xconv_kernel<<<(threads + 255) / 256, 256>>>(ei, x, E);
    }
    scanA_kernel<<<SCAN_BLOCKS, 1024>>>();
    scanB_kernel<<<1, 128>>>();
    scanC_kernel<<<SCAN_BLOCKS, 1024>>>();
    {
        int threads = (E + 3) / 4;
        fill_kernel<<<(threads + 255) / 256, 256>>>(ei, E);
    }
    {   // agg1
        unsigned total = (unsigned)N_NODES * 32u;
        agg1_kernel<<<(total + 255) / 256, 256>>>();
    }
    cudaStreamWaitEvent(0, ev_join, 0);
    gemm1_kernel<<<gemmBlocks, 256>>>(W1l);
    gemm2_kernel<<<gemmBlocks, 256>>>(W2l, b2l, W2r, out);
    {   // agg2 + final add
        unsigned total = (unsigned)N_NODES * 32u;
        agg2_kernel<<<(total + 255) / 256, 256>>>(out);
    }
}

// round 10
// speedup vs baseline: 1.7550x; 1.1085x over previous
#include <cuda_runtime.h>
#include <cuda_fp16.h>
#include <cstdint>

#define N_NODES 100000
#define N_EDGES_MAX 3200000
#define IN_C 64
#define HID_C 64
#define OUT_C 32
#define SCAN_BLOCKS 98   // 98 * 1024 >= N_NODES

// Scratch (static __device__ arrays per harness rules)
__device__ __align__(16) float  g_sum1[(size_t)N_NODES * HID_C];  // mean-agg L1
__device__ __align__(16) float  g_pre [(size_t)N_NODES * HID_C];  // x@W1r + b1l
__device__ __align__(16) __half g_xh  [(size_t)N_NODES * IN_C];   // x in fp16
__device__ __align__(16) __half g_p2h [(size_t)N_NODES * OUT_C];  // h@W2l fp16
__device__ __align__(16) int    g_csr [N_EDGES_MAX];
__device__ __align__(16) int    g_rank[N_EDGES_MAX];
__device__ __align__(16) int    g_degi[N_NODES];
__device__ __align__(16) int    g_rowstart[N_NODES + 1];
__device__ __align__(16) int    g_bsum[SCAN_BLOCKS];
__device__ int g_scan_count;

static __device__ __forceinline__ unsigned h2_bits(__half2 h) {
    return *reinterpret_cast<const unsigned*>(&h);
}
static __device__ __forceinline__ float2 u32_to_f2(unsigned u) {
    return __half22float2(*reinterpret_cast<const __half2*>(&u));
}
// --- packed f32x2 helpers (FFMA2; PTX-only) ---
static __device__ __forceinline__ unsigned long long dup2(float v) {
    unsigned long long r;
    asm("mov.b64 %0, {%1, %1};" : "=l"(r) : "f"(v));
    return r;
}
static __device__ __forceinline__ unsigned long long fma2(
    unsigned long long a, unsigned long long b, unsigned long long c) {
    unsigned long long d;
    asm("fma.rn.f32x2 %0, %1, %2, %3;" : "=l"(d) : "l"(a), "l"(b), "l"(c));
    return d;
}
static __device__ __forceinline__ void unpack2(unsigned long long v,
                                               float& lo, float& hi) {
    asm("mov.b64 {%0, %1}, %2;" : "=f"(lo), "=f"(hi) : "l"(v));
}

// ---------------------------------------------------------------------------
// Kernel 1: degree histogram + per-edge rank (atomic return) + x -> fp16.
// ---------------------------------------------------------------------------
__global__ void hist_xconv_kernel(const int* __restrict__ ei,
                                  const float* __restrict__ x, int E) {
    int t = blockIdx.x * blockDim.x + threadIdx.x;
    int e0 = t * 4;
    int d[4];
#pragma unroll
    for (int j = 0; j < 4; j++) {
        int e = e0 + j;
        if (e < E) d[j] = ei[(size_t)E + e];
    }
    int r[4];
#pragma unroll
    for (int j = 0; j < 4; j++) {
        int e = e0 + j;
        if (e < E) r[j] = atomicAdd(&g_degi[d[j]], 1);
    }
#pragma unroll
    for (int j = 0; j < 4; j++) {
        int e = e0 + j;
        if (e < E) g_rank[e] = r[j];
    }
    size_t xi = (size_t)t * 8;
    if (xi + 8 <= (size_t)N_NODES * IN_C) {
        float4 f0 = ((const float4*)x)[t * 2];
        float4 f1 = ((const float4*)x)[t * 2 + 1];
        __half2 h0 = __floats2half2_rn(f0.x, f0.y);
        __half2 h1 = __floats2half2_rn(f0.z, f0.w);
        __half2 h2 = __floats2half2_rn(f1.x, f1.y);
        __half2 h3 = __floats2half2_rn(f1.z, f1.w);
        uint4 packed = make_uint4(h2_bits(h0), h2_bits(h1), h2_bits(h2), h2_bits(h3));
        ((uint4*)g_xh)[t] = packed;
    }
}

// ---------------------------------------------------------------------------
// Kernel 2: fused scan (single kernel, global barrier via atomic counter).
// All SCAN_BLOCKS blocks are co-resident (98 <= 148 SMs) -> spin is safe.
// ---------------------------------------------------------------------------
__global__ __launch_bounds__(1024) void scan_fused_kernel() {
    __shared__ int ssum[1024];
    __shared__ int sbs[128];
    __shared__ int sorig[128];
    __shared__ int s_boff;
    int t = threadIdx.x;
    int b = blockIdx.x;
    int node = b * 1024 + t;
    int v = (node < N_NODES) ? g_degi[node] : 0;
    ssum[t] = v;
    __syncthreads();
    for (int off = 1; off < 1024; off <<= 1) {
        int u = (t >= off) ? ssum[t - off] : 0;
        __syncthreads();
        ssum[t] += u;
        __syncthreads();
    }
    int lexcl = ssum[t] - v;
    if (t == 1023) {
        g_bsum[b] = ssum[t];
        __threadfence();
        atomicAdd(&g_scan_count, 1);
    }
    if (t == 0) {
        while (atomicAdd(&g_scan_count, 0) < SCAN_BLOCKS) { }
    }
    __syncthreads();
    __threadfence();
    // every block scans the 98 block sums (redundant but tiny)
    int bv = (t < SCAN_BLOCKS) ? g_bsum[t] : 0;
    if (t < 128) { sbs[t] = bv; sorig[t] = bv; }
    __syncthreads();
    for (int off = 1; off < 128; off <<= 1) {
        int u = (t >= off && t < 128) ? sbs[t - off] : 0;
        __syncthreads();
        if (t < 128) sbs[t] += u;
        __syncthreads();
    }
    if (t == 0) s_boff = sbs[b] - sorig[b];   // exclusive offset of this block
    __syncthreads();
    if (node < N_NODES) g_rowstart[node] = lexcl + s_boff;
    if (b == 0 && t == 0) g_rowstart[N_NODES] = sbs[SCAN_BLOCKS - 1];
}

// ---------------------------------------------------------------------------
// Kernel 3: fill CSR — no atomics (pos = rowstart[dst] + rank[e]).
// ---------------------------------------------------------------------------
__global__ void fill_kernel(const int* __restrict__ ei, int E) {
    int e0 = (blockIdx.x * blockDim.x + threadIdx.x) * 4;
    int s[4], d[4], r[4];
#pragma unroll
    for (int j = 0; j < 4; j++) {
        int e = e0 + j;
        if (e < E) {
            s[j] = ei[e];
            d[j] = ei[(size_t)E + e];
            r[j] = g_rank[e];
        }
    }
    int base[4];
#pragma unroll
    for (int j = 0; j < 4; j++) {
        int e = e0 + j;
        if (e < E) base[j] = g_rowstart[d[j]];
    }
#pragma unroll
    for (int j = 0; j < 4; j++) {
        int e = e0 + j;
        if (e < E) g_csr[base[j] + r[j]] = s[j];
    }
}

// ---------------------------------------------------------------------------
// Kernel 4 (PROFILED): agg1 — one warp per dst node; 2 neighbors per round.
// ---------------------------------------------------------------------------
__global__ __launch_bounds__(256) void agg1_kernel() {
    int warp = (blockIdx.x * blockDim.x + threadIdx.x) >> 5;
    if (warp >= N_NODES) return;
    unsigned lane = threadIdx.x & 31;
    unsigned half = lane >> 4;
    unsigned l    = lane & 15;
    int row = g_rowstart[warp];
    int n   = g_rowstart[warp + 1] - row;
    const int* cs = g_csr + row;
    const uint2* xh2 = (const uint2*)g_xh;
    float4 a0 = make_float4(0.f, 0.f, 0.f, 0.f);
    float4 a1 = a0, a2 = a0, a3 = a0;
    int k = 0;
    for (; k + 8 <= n; k += 8) {
        unsigned i0 = (unsigned)cs[k + 0 + half] * 16u + l;
        unsigned i1 = (unsigned)cs[k + 2 + half] * 16u + l;
        unsigned i2 = (unsigned)cs[k + 4 + half] * 16u + l;
        unsigned i3 = (unsigned)cs[k + 6 + half] * 16u + l;
        uint2 u0 = xh2[i0];
        uint2 u1 = xh2[i1];
        uint2 u2 = xh2[i2];
        uint2 u3 = xh2[i3];
        float2 f;
        f = u32_to_f2(u0.x); a0.x += f.x; a0.y += f.y;
        f = u32_to_f2(u0.y); a0.z += f.x; a0.w += f.y;
        f = u32_to_f2(u1.x); a1.x += f.x; a1.y += f.y;
        f = u32_to_f2(u1.y); a1.z += f.x; a1.w += f.y;
        f = u32_to_f2(u2.x); a2.x += f.x; a2.y += f.y;
        f = u32_to_f2(u2.y); a2.z += f.x; a2.w += f.y;
        f = u32_to_f2(u3.x); a3.x += f.x; a3.y += f.y;
        f = u32_to_f2(u3.y); a3.z += f.x; a3.w += f.y;
    }
    for (; k < n; k += 2) {
        int e = k + half;
        uint2 u = make_uint2(0u, 0u);
        if (e < n) u = xh2[(unsigned)cs[e] * 16u + l];
        float2 f;
        f = u32_to_f2(u.x); a0.x += f.x; a0.y += f.y;
        f = u32_to_f2(u.y); a0.z += f.x; a0.w += f.y;
    }
    float4 s;
    s.x = (a0.x + a1.x) + (a2.x + a3.x);
    s.y = (a0.y + a1.y) + (a2.y + a3.y);
    s.z = (a0.z + a1.z) + (a2.z + a3.z);
    s.w = (a0.w + a1.w) + (a2.w + a3.w);
    s.x += __shfl_xor_sync(0xffffffffu, s.x, 16);
    s.y += __shfl_xor_sync(0xffffffffu, s.y, 16);
    s.z += __shfl_xor_sync(0xffffffffu, s.z, 16);
    s.w += __shfl_xor_sync(0xffffffffu, s.w, 16);
    if (half == 0) {
        float invd = 1.0f / (float)max(n, 1);
        float4 r;
        r.x = s.x * invd; r.y = s.y * invd; r.z = s.z * invd; r.w = s.w * invd;
        ((float4*)g_sum1)[(unsigned)warp * 16u + l] = r;
    }
}

// ---------------------------------------------------------------------------
// FFMA2 GEMM cores. Global-A variant clamps node; smem-A variant uses local row.
// ---------------------------------------------------------------------------
#define GEMM_CORE(A4, sB, accP, nodeBase, cg)                                 \
    {                                                                         \
        const ulonglong2* sBp = (const ulonglong2*)(sB);                      \
        _Pragma("unroll 4")                                                   \
        for (int k4 = 0; k4 < 16; k4++) {                                     \
            ulonglong2 b0 = sBp[(k4 * 4 + 0) * 16 + (cg)];                    \
            ulonglong2 b1 = sBp[(k4 * 4 + 1) * 16 + (cg)];                    \
            ulonglong2 b2 = sBp[(k4 * 4 + 2) * 16 + (cg)];                    \
            ulonglong2 b3 = sBp[(k4 * 4 + 3) * 16 + (cg)];                    \
            _Pragma("unroll")                                                 \
            for (int m = 0; m < 8; m++) {                                     \
                int node = min((nodeBase) + m, N_NODES - 1);                  \
                float4 a = (A4)[(size_t)node * 16 + k4];                      \
                unsigned long long ax = dup2(a.x), ay = dup2(a.y);            \
                unsigned long long az = dup2(a.z), aw = dup2(a.w);            \
                accP[m][0] = fma2(ax, b0.x, accP[m][0]);                      \
                accP[m][1] = fma2(ax, b0.y, accP[m][1]);                      \
                accP[m][0] = fma2(ay, b1.x, accP[m][0]);                      \
                accP[m][1] = fma2(ay, b1.y, accP[m][1]);                      \
                accP[m][0] = fma2(az, b2.x, accP[m][0]);                      \
                accP[m][1] = fma2(az, b2.y, accP[m][1]);                      \
                accP[m][0] = fma2(aw, b3.x, accP[m][0]);                      \
                accP[m][1] = fma2(aw, b3.y, accP[m][1]);                      \
            }                                                                 \
        }                                                                     \
    }

#define GEMM_CORE_L(A4, sB, accP, lbase, cg)                                  \
    {                                                                         \
        const ulonglong2* sBp = (const ulonglong2*)(sB);                      \
        _Pragma("unroll 4")                                                   \
        for (int k4 = 0; k4 < 16; k4++) {                                     \
            ulonglong2 b0 = sBp[(k4 * 4 + 0) * 16 + (cg)];                    \
            ulonglong2 b1 = sBp[(k4 * 4 + 1) * 16 + (cg)];                    \
            ulonglong2 b2 = sBp[(k4 * 4 + 2) * 16 + (cg)];                    \
            ulonglong2 b3 = sBp[(k4 * 4 + 3) * 16 + (cg)];                    \
            _Pragma("unroll")                                                 \
            for (int m = 0; m < 8; m++) {                                     \
                int lrow = (lbase) + m;                                       \
                float4 a = (A4)[lrow * 16 + k4];                              \
                unsigned long long ax = dup2(a.x), ay = dup2(a.y);            \
                unsigned long long az = dup2(a.z), aw = dup2(a.w);            \
                accP[m][0] = fma2(ax, b0.x, accP[m][0]);                      \
                accP[m][1] = fma2(ax, b0.y, accP[m][1]);                      \
                accP[m][0] = fma2(ay, b1.x, accP[m][0]);                      \
                accP[m][1] = fma2(ay, b1.y, accP[m][1]);                      \
                accP[m][0] = fma2(az, b2.x, accP[m][0]);                      \
                accP[m][1] = fma2(az, b2.y, accP[m][1]);                      \
                accP[m][0] = fma2(aw, b3.x, accP[m][0]);                      \
                accP[m][1] = fma2(aw, b3.y, accP[m][1]);                      \
            }                                                                 \
        }                                                                     \
    }

// ---------------------------------------------------------------------------
// Kernel: gemmR — pre = x @ W1r + b1l  (side stream; overlaps CSR build)
// ---------------------------------------------------------------------------
__global__ __launch_bounds__(256) void gemmR_kernel(
    const float* __restrict__ x, const float* __restrict__ W1r,
    const float* __restrict__ b1l) {
    __shared__ float sB[64 * 64];
    int t  = threadIdx.x;
    int cg = t & 15;
    int ng = t >> 4;
    int nodeBase = blockIdx.x * 128 + ng * 8;

    unsigned long long accP[8][2];
#pragma unroll
    for (int m = 0; m < 8; m++) { accP[m][0] = 0ull; accP[m][1] = 0ull; }

#pragma unroll
    for (int i = 0; i < 4; i++) {
        int f4 = t + i * 256;
        ((float4*)sB)[f4] = ((const float4*)W1r)[f4];
    }
    __syncthreads();
    GEMM_CORE((const float4*)x, sB, accP, nodeBase, cg)
    float4 bias = ((const float4*)b1l)[cg];
#pragma unroll
    for (int m = 0; m < 8; m++) {
        int node = nodeBase + m;
        if (node < N_NODES) {
            float4 r;
            unpack2(accP[m][0], r.x, r.y);
            unpack2(accP[m][1], r.z, r.w);
            r.x += bias.x; r.y += bias.y; r.z += bias.z; r.w += bias.w;
            ((float4*)(g_pre + (size_t)node * 64))[cg] = r;
        }
    }
}

// ---------------------------------------------------------------------------
// Kernel: gemm12 — fused layer-1 + layer-2 node GEMMs.
//   h(tile, smem) = relu( sum1 @ W1l + pre )
//   p2h = (h @ W2l) fp16 ; out = h @ W2r + b2l
// ---------------------------------------------------------------------------
__global__ __launch_bounds__(256) void gemm12_kernel(
    const float* __restrict__ W1l,
    const float* __restrict__ W2l, const float* __restrict__ b2l,
    const float* __restrict__ W2r, float* __restrict__ out) {
    __shared__ float sB[64 * 64];     // 16 KB
    __shared__ float sH[128 * 64];    // 32 KB
    int t  = threadIdx.x;
    int cg = t & 15;
    int ng = t >> 4;
    int nodeBase = blockIdx.x * 128 + ng * 8;

    unsigned long long accP[8][2];
#pragma unroll
    for (int m = 0; m < 8; m++) { accP[m][0] = 0ull; accP[m][1] = 0ull; }

    // ---- pass 1: h = relu(sum1 @ W1l + pre) ----
#pragma unroll
    for (int i = 0; i < 4; i++) {
        int f4 = t + i * 256;
        ((float4*)sB)[f4] = ((const float4*)W1l)[f4];
    }
    __syncthreads();
    GEMM_CORE((const float4*)g_sum1, sB, accP, nodeBase, cg)
#pragma unroll
    for (int m = 0; m < 8; m++) {
        int cn = min(nodeBase + m, N_NODES - 1);
        float4 p = ((const float4*)(g_pre + (size_t)cn * 64))[cg];
        float4 r;
        unpack2(accP[m][0], r.x, r.y);
        unpack2(accP[m][1], r.z, r.w);
        r.x = fmaxf(r.x + p.x, 0.f);
        r.y = fmaxf(r.y + p.y, 0.f);
        r.z = fmaxf(r.z + p.z, 0.f);
        r.w = fmaxf(r.w + p.w, 0.f);
        ((float4*)(sH + (ng * 8 + m) * 64))[cg] = r;
    }
    __syncthreads();

    // ---- pass 2: stage combined W2 (cols 0-31 W2l, 32-63 W2r) ----
#pragma unroll
    for (int i = 0; i < 4; i++) {
        int f4 = t + i * 256;
        int k  = f4 >> 4;
        int jq = f4 & 15;
        float4 v = (jq < 8) ? ((const float4*)W2l)[k * 8 + jq]
                            : ((const float4*)W2r)[k * 8 + (jq - 8)];
        ((float4*)sB)[f4] = v;
    }
#pragma unroll
    for (int m = 0; m < 8; m++) { accP[m][0] = 0ull; accP[m][1] = 0ull; }
    __syncthreads();
    GEMM_CORE_L((const float4*)sH, sB, accP, ng * 8, cg)
#pragma unroll
    for (int m = 0; m < 8; m++) {
        int node = nodeBase + m;
        if (node < N_NODES) {
            float4 r;
            unpack2(accP[m][0], r.x, r.y);
            unpack2(accP[m][1], r.z, r.w);
            if (cg < 8) {
                __half2 h0 = __floats2half2_rn(r.x, r.y);
                __half2 h1 = __floats2half2_rn(r.z, r.w);
                uint2 packed = make_uint2(h2_bits(h0), h2_bits(h1));
                ((uint2*)(g_p2h + (size_t)node * 32))[cg] = packed;
            } else {
                float4 bias = ((const float4*)b2l)[cg - 8];
                r.x += bias.x; r.y += bias.y; r.z += bias.z; r.w += bias.w;
                ((float4*)(out + (size_t)node * 32))[cg - 8] = r;
            }
        }
    }
}

// ---------------------------------------------------------------------------
// Kernel: agg2 + final — one warp per node; 4 neighbors per round.
// ---------------------------------------------------------------------------
__global__ __launch_bounds__(256) void agg2_kernel(float* __restrict__ out) {
    int warp = (blockIdx.x * blockDim.x + threadIdx.x) >> 5;
    if (warp >= N_NODES) return;
    unsigned lane = threadIdx.x & 31;
    unsigned g    = lane >> 3;
    unsigned l    = lane & 7;
    int row = g_rowstart[warp];
    int n   = g_rowstart[warp + 1] - row;
    const int* cs = g_csr + row;
    const uint2* p2 = (const uint2*)g_p2h;
    float4 a0 = make_float4(0.f, 0.f, 0.f, 0.f);
    float4 a1 = a0, a2 = a0, a3 = a0;
    int k = 0;
    for (; k + 16 <= n; k += 16) {
        unsigned i0 = (unsigned)cs[k + 0  + g] * 8u + l;
        unsigned i1 = (unsigned)cs[k + 4  + g] * 8u + l;
        unsigned i2 = (unsigned)cs[k + 8  + g] * 8u + l;
        unsigned i3 = (unsigned)cs[k + 12 + g] * 8u + l;
        uint2 u0 = p2[i0];
        uint2 u1 = p2[i1];
        uint2 u2 = p2[i2];
        uint2 u3 = p2[i3];
        float2 f;
        f = u32_to_f2(u0.x); a0.x += f.x; a0.y += f.y;
        f = u32_to_f2(u0.y); a0.z += f.x; a0.w += f.y;
        f = u32_to_f2(u1.x); a1.x += f.x; a1.y += f.y;
        f = u32_to_f2(u1.y); a1.z += f.x; a1.w += f.y;
        f = u32_to_f2(u2.x); a2.x += f.x; a2.y += f.y;
        f = u32_to_f2(u2.y); a2.z += f.x; a2.w += f.y;
        f = u32_to_f2(u3.x); a3.x += f.x; a3.y += f.y;
        f = u32_to_f2(u3.y); a3.z += f.x; a3.w += f.y;
    }
    for (; k < n; k += 4) {
        int e = k + g;
        uint2 u = make_uint2(0u, 0u);
        if (e < n) u = p2[(unsigned)cs[e] * 8u + l];
        float2 f;
        f = u32_to_f2(u.x); a0.x += f.x; a0.y += f.y;
        f = u32_to_f2(u.y); a0.z += f.x; a0.w += f.y;
    }
    float4 s;
    s.x = (a0.x + a1.x) + (a2.x + a3.x);
    s.y = (a0.y + a1.y) + (a2.y + a3.y);
    s.z = (a0.z + a1.z) + (a2.z + a3.z);
    s.w = (a0.w + a1.w) + (a2.w + a3.w);
#pragma unroll
    for (int off = 8; off <= 16; off <<= 1) {
        s.x += __shfl_xor_sync(0xffffffffu, s.x, off);
        s.y += __shfl_xor_sync(0xffffffffu, s.y, off);
        s.z += __shfl_xor_sync(0xffffffffu, s.z, off);
        s.w += __shfl_xor_sync(0xffffffffu, s.w, off);
    }
    if (lane < 8) {
        float invd = 1.0f / (float)max(n, 1);
        unsigned oi = (unsigned)warp * 8u + l;
        float4 o = ((float4*)out)[oi];
        o.x = fmaf(s.x, invd, o.x);
        o.y = fmaf(s.y, invd, o.y);
        o.z = fmaf(s.z, invd, o.z);
        o.w = fmaf(s.w, invd, o.w);
        ((float4*)out)[oi] = o;
    }
}

extern "C" void kernel_launch(void* const* d_in, const int* in_sizes, int n_in,
                              void* d_out, int out_size) {
    const float* x   = (const float*)d_in[0];
    const int*   ei  = (const int*)d_in[1];   // int32
    const float* W1l = (const float*)d_in[2];
    const float* b1l = (const float*)d_in[3];
    const float* W1r = (const float*)d_in[4];
    const float* W2l = (const float*)d_in[5];
    const float* b2l = (const float*)d_in[6];
    const float* W2r = (const float*)d_in[7];
    float* out = (float*)d_out;
    int E = in_sizes[1] / 2;

    static cudaStream_t s_side = nullptr;
    static cudaEvent_t  ev_fork = nullptr, ev_join = nullptr;
    if (s_side == nullptr) {
        cudaStreamCreateWithFlags(&s_side, cudaStreamNonBlocking);
        cudaEventCreateWithFlags(&ev_fork, cudaEventDisableTiming);
        cudaEventCreateWithFlags(&ev_join, cudaEventDisableTiming);
    }

    // Fork event first: side-stream work depends on nothing upstream.
    cudaEventRecord(ev_fork, 0);
    cudaStreamWaitEvent(s_side, ev_fork, 0);

    void *p_degi, *p_cnt;
    cudaGetSymbolAddress(&p_degi, g_degi);
    cudaGetSymbolAddress(&p_cnt,  g_scan_count);
    cudaMemsetAsync(p_degi, 0, (size_t)N_NODES * sizeof(int), 0);
    cudaMemsetAsync(p_cnt,  0, sizeof(int), 0);

    int gemmBlocks = (N_NODES + 127) / 128;

    {   // kernel 1: hist + rank + x->fp16
        int tE = (E + 3) / 4;
        int tX = (N_NODES * IN_C + 7) / 8;
        int threads = tE > tX ? tE : tX;
        hist_xconv_kernel<<<(threads + 255) / 256, 256>>>(ei, x, E);
    }
    scan_fused_kernel<<<SCAN_BLOCKS, 1024>>>();       // kernel 2
    {
        int threads = (E + 3) / 4;                    // kernel 3
        fill_kernel<<<(threads + 255) / 256, 256>>>(ei, E);
    }
    {   // kernel 4 (profiled): agg1
        unsigned total = (unsigned)N_NODES * 32u;
        agg1_kernel<<<(total + 255) / 256, 256>>>();
    }
    // gemmR launched now (host order) but gated only on ev_fork -> overlaps
    // the CSR build + agg1 execution.
    gemmR_kernel<<<gemmBlocks, 256, 0, s_side>>>(x, W1r, b1l);
    cudaEventRecord(ev_join, s_side);
    cudaStreamWaitEvent(0, ev_join, 0);

    gemm12_kernel<<<gemmBlocks, 256>>>(W1l, W2l, b2l, W2r, out);
    {   // agg2 + final add
        unsigned total = (unsigned)N_NODES * 32u;
        agg2_kernel<<<(total + 255) / 256, 256>>>(out);
    }
}

// round 11
// speedup vs baseline: 1.9908x; 1.1344x over previous
#include <cuda_runtime.h>
#include <cuda_fp16.h>
#include <cstdint>

#define N_NODES 100000
#define N_EDGES_MAX 3200000
#define IN_C 64
#define HID_C 64
#define OUT_C 32
#define SCAN_BLOCKS 98   // 98 * 1024 >= N_NODES

// Scratch (static __device__ arrays per harness rules)
__device__ __align__(16) float  g_sum1[(size_t)N_NODES * HID_C];  // mean-agg L1
__device__ __align__(16) float  g_pre [(size_t)N_NODES * HID_C];  // x@W1r + b1l
__device__ __align__(16) __half g_xh  [(size_t)N_NODES * IN_C];   // x in fp16
__device__ __align__(16) __half g_p2h [(size_t)N_NODES * OUT_C];  // h@W2l fp16
__device__ __align__(16) int    g_csr [N_EDGES_MAX];
__device__ __align__(16) int    g_rank[N_EDGES_MAX];
__device__ __align__(16) int    g_degi[N_NODES];
__device__ __align__(16) int    g_rowstart[N_NODES + 1];
__device__ __align__(16) int    g_bsum[SCAN_BLOCKS];
__device__ int g_scan_count;

static __device__ __forceinline__ unsigned h2_bits(__half2 h) {
    return *reinterpret_cast<const unsigned*>(&h);
}
static __device__ __forceinline__ __half2 u2h(unsigned u) {
    return *reinterpret_cast<const __half2*>(&u);
}
static __device__ __forceinline__ float2 u32_to_f2(unsigned u) {
    return __half22float2(*reinterpret_cast<const __half2*>(&u));
}
// --- packed f32x2 helpers (FFMA2; PTX-only) ---
static __device__ __forceinline__ unsigned long long dup2(float v) {
    unsigned long long r;
    asm("mov.b64 %0, {%1, %1};" : "=l"(r) : "f"(v));
    return r;
}
static __device__ __forceinline__ unsigned long long fma2(
    unsigned long long a, unsigned long long b, unsigned long long c) {
    unsigned long long d;
    asm("fma.rn.f32x2 %0, %1, %2, %3;" : "=l"(d) : "l"(a), "l"(b), "l"(c));
    return d;
}
static __device__ __forceinline__ void unpack2(unsigned long long v,
                                               float& lo, float& hi) {
    asm("mov.b64 {%0, %1}, %2;" : "=f"(lo), "=f"(hi) : "l"(v));
}

// ---------------------------------------------------------------------------
// Kernel 1: degree histogram + per-edge rank (atomic return) + x -> fp16.
// ---------------------------------------------------------------------------
__global__ void hist_xconv_kernel(const int* __restrict__ ei,
                                  const float* __restrict__ x, int E) {
    int t = blockIdx.x * blockDim.x + threadIdx.x;
    int e0 = t * 4;
    int d[4];
#pragma unroll
    for (int j = 0; j < 4; j++) {
        int e = e0 + j;
        if (e < E) d[j] = ei[(size_t)E + e];
    }
    int r[4];
#pragma unroll
    for (int j = 0; j < 4; j++) {
        int e = e0 + j;
        if (e < E) r[j] = atomicAdd(&g_degi[d[j]], 1);
    }
#pragma unroll
    for (int j = 0; j < 4; j++) {
        int e = e0 + j;
        if (e < E) g_rank[e] = r[j];
    }
    size_t xi = (size_t)t * 8;
    if (xi + 8 <= (size_t)N_NODES * IN_C) {
        float4 f0 = ((const float4*)x)[t * 2];
        float4 f1 = ((const float4*)x)[t * 2 + 1];
        __half2 h0 = __floats2half2_rn(f0.x, f0.y);
        __half2 h1 = __floats2half2_rn(f0.z, f0.w);
        __half2 h2 = __floats2half2_rn(f1.x, f1.y);
        __half2 h3 = __floats2half2_rn(f1.z, f1.w);
        uint4 packed = make_uint4(h2_bits(h0), h2_bits(h1), h2_bits(h2), h2_bits(h3));
        ((uint4*)g_xh)[t] = packed;
    }
}

// ---------------------------------------------------------------------------
// Kernel 2: fused scan (single kernel, global barrier via atomic counter).
// ---------------------------------------------------------------------------
__global__ __launch_bounds__(1024) void scan_fused_kernel() {
    __shared__ int ssum[1024];
    __shared__ int sbs[128];
    __shared__ int sorig[128];
    __shared__ int s_boff;
    int t = threadIdx.x;
    int b = blockIdx.x;
    int node = b * 1024 + t;
    int v = (node < N_NODES) ? g_degi[node] : 0;
    ssum[t] = v;
    __syncthreads();
    for (int off = 1; off < 1024; off <<= 1) {
        int u = (t >= off) ? ssum[t - off] : 0;
        __syncthreads();
        ssum[t] += u;
        __syncthreads();
    }
    int lexcl = ssum[t] - v;
    if (t == 1023) {
        g_bsum[b] = ssum[t];
        __threadfence();
        atomicAdd(&g_scan_count, 1);
    }
    if (t == 0) {
        while (atomicAdd(&g_scan_count, 0) < SCAN_BLOCKS) { }
    }
    __syncthreads();
    __threadfence();
    int bv = (t < SCAN_BLOCKS) ? g_bsum[t] : 0;
    if (t < 128) { sbs[t] = bv; sorig[t] = bv; }
    __syncthreads();
    for (int off = 1; off < 128; off <<= 1) {
        int u = (t >= off && t < 128) ? sbs[t - off] : 0;
        __syncthreads();
        if (t < 128) sbs[t] += u;
        __syncthreads();
    }
    if (t == 0) s_boff = sbs[b] - sorig[b];
    __syncthreads();
    if (node < N_NODES) g_rowstart[node] = lexcl + s_boff;
    if (b == 0 && t == 0) g_rowstart[N_NODES] = sbs[SCAN_BLOCKS - 1];
}

// ---------------------------------------------------------------------------
// Kernel 3: fill CSR — no atomics (pos = rowstart[dst] + rank[e]).
// ---------------------------------------------------------------------------
__global__ void fill_kernel(const int* __restrict__ ei, int E) {
    int e0 = (blockIdx.x * blockDim.x + threadIdx.x) * 4;
    int s[4], d[4], r[4];
#pragma unroll
    for (int j = 0; j < 4; j++) {
        int e = e0 + j;
        if (e < E) {
            s[j] = ei[e];
            d[j] = ei[(size_t)E + e];
            r[j] = g_rank[e];
        }
    }
    int base[4];
#pragma unroll
    for (int j = 0; j < 4; j++) {
        int e = e0 + j;
        if (e < E) base[j] = g_rowstart[d[j]];
    }
#pragma unroll
    for (int j = 0; j < 4; j++) {
        int e = e0 + j;
        if (e < E) g_csr[base[j] + r[j]] = s[j];
    }
}

// ---------------------------------------------------------------------------
// Kernel 4 (PROFILED): agg1 — one warp per dst node; 2 neighbors per round.
// fp16 tree-sum over each 4-neighbor group, then one fp32 accumulate.
// ---------------------------------------------------------------------------
__global__ __launch_bounds__(256) void agg1_kernel() {
    int warp = (blockIdx.x * blockDim.x + threadIdx.x) >> 5;
    if (warp >= N_NODES) return;
    unsigned lane = threadIdx.x & 31;
    unsigned half = lane >> 4;
    unsigned l    = lane & 15;
    int row = g_rowstart[warp];
    int n   = g_rowstart[warp + 1] - row;
    const int* cs = g_csr + row;
    const uint2* xh2 = (const uint2*)g_xh;
    float4 acc = make_float4(0.f, 0.f, 0.f, 0.f);
    int k = 0;
    for (; k + 8 <= n; k += 8) {
        unsigned i0 = (unsigned)cs[k + 0 + half] * 16u + l;
        unsigned i1 = (unsigned)cs[k + 2 + half] * 16u + l;
        unsigned i2 = (unsigned)cs[k + 4 + half] * 16u + l;
        unsigned i3 = (unsigned)cs[k + 6 + half] * 16u + l;
        uint2 u0 = xh2[i0];
        uint2 u1 = xh2[i1];
        uint2 u2 = xh2[i2];
        uint2 u3 = xh2[i3];
        // fp16 tree over the 4 neighbors (same features), then fp32 add
        __half2 sx = __hadd2(__hadd2(u2h(u0.x), u2h(u1.x)),
                             __hadd2(u2h(u2.x), u2h(u3.x)));
        __half2 sy = __hadd2(__hadd2(u2h(u0.y), u2h(u1.y)),
                             __hadd2(u2h(u2.y), u2h(u3.y)));
        float2 fx = __half22float2(sx);
        float2 fy = __half22float2(sy);
        acc.x += fx.x; acc.y += fx.y; acc.z += fy.x; acc.w += fy.y;
    }
    for (; k < n; k += 2) {
        int e = k + half;
        uint2 u = make_uint2(0u, 0u);
        if (e < n) u = xh2[(unsigned)cs[e] * 16u + l];
        float2 fx = u32_to_f2(u.x);
        float2 fy = u32_to_f2(u.y);
        acc.x += fx.x; acc.y += fx.y; acc.z += fy.x; acc.w += fy.y;
    }
    acc.x += __shfl_xor_sync(0xffffffffu, acc.x, 16);
    acc.y += __shfl_xor_sync(0xffffffffu, acc.y, 16);
    acc.z += __shfl_xor_sync(0xffffffffu, acc.z, 16);
    acc.w += __shfl_xor_sync(0xffffffffu, acc.w, 16);
    if (half == 0) {
        float invd = 1.0f / (float)max(n, 1);
        float4 r;
        r.x = acc.x * invd; r.y = acc.y * invd;
        r.z = acc.z * invd; r.w = acc.w * invd;
        ((float4*)g_sum1)[(unsigned)warp * 16u + l] = r;
    }
}

// ---------------------------------------------------------------------------
// FFMA2 GEMM cores.
// ---------------------------------------------------------------------------
#define GEMM_CORE(A4, sB, accP, nodeBase, cg)                                 \
    {                                                                         \
        const ulonglong2* sBp = (const ulonglong2*)(sB);                      \
        _Pragma("unroll 4")                                                   \
        for (int k4 = 0; k4 < 16; k4++) {                                     \
            ulonglong2 b0 = sBp[(k4 * 4 + 0) * 16 + (cg)];                    \
            ulonglong2 b1 = sBp[(k4 * 4 + 1) * 16 + (cg)];                    \
            ulonglong2 b2 = sBp[(k4 * 4 + 2) * 16 + (cg)];                    \
            ulonglong2 b3 = sBp[(k4 * 4 + 3) * 16 + (cg)];                    \
            _Pragma("unroll")                                                 \
            for (int m = 0; m < 8; m++) {                                     \
                int node = min((nodeBase) + m, N_NODES - 1);                  \
                float4 a = (A4)[(size_t)node * 16 + k4];                      \
                unsigned long long ax = dup2(a.x), ay = dup2(a.y);            \
                unsigned long long az = dup2(a.z), aw = dup2(a.w);            \
                accP[m][0] = fma2(ax, b0.x, accP[m][0]);                      \
                accP[m][1] = fma2(ax, b0.y, accP[m][1]);                      \
                accP[m][0] = fma2(ay, b1.x, accP[m][0]);                      \
                accP[m][1] = fma2(ay, b1.y, accP[m][1]);                      \
                accP[m][0] = fma2(az, b2.x, accP[m][0]);                      \
                accP[m][1] = fma2(az, b2.y, accP[m][1]);                      \
                accP[m][0] = fma2(aw, b3.x, accP[m][0]);                      \
                accP[m][1] = fma2(aw, b3.y, accP[m][1]);                      \
            }                                                                 \
        }                                                                     \
    }

#define GEMM_CORE_L(A4, sB, accP, lbase, cg)                                  \
    {                                                                         \
        const ulonglong2* sBp = (const ulonglong2*)(sB);                      \
        _Pragma("unroll 4")                                                   \
        for (int k4 = 0; k4 < 16; k4++) {                                     \
            ulonglong2 b0 = sBp[(k4 * 4 + 0) * 16 + (cg)];                    \
            ulonglong2 b1 = sBp[(k4 * 4 + 1) * 16 + (cg)];                    \
            ulonglong2 b2 = sBp[(k4 * 4 + 2) * 16 + (cg)];                    \
            ulonglong2 b3 = sBp[(k4 * 4 + 3) * 16 + (cg)];                    \
            _Pragma("unroll")                                                 \
            for (int m = 0; m < 8; m++) {                                     \
                int lrow = (lbase) + m;                                       \
                float4 a = (A4)[lrow * 16 + k4];                              \
                unsigned long long ax = dup2(a.x), ay = dup2(a.y);            \
                unsigned long long az = dup2(a.z), aw = dup2(a.w);            \
                accP[m][0] = fma2(ax, b0.x, accP[m][0]);                      \
                accP[m][1] = fma2(ax, b0.y, accP[m][1]);                      \
                accP[m][0] = fma2(ay, b1.x, accP[m][0]);                      \
                accP[m][1] = fma2(ay, b1.y, accP[m][1]);                      \
                accP[m][0] = fma2(az, b2.x, accP[m][0]);                      \
                accP[m][1] = fma2(az, b2.y, accP[m][1]);                      \
                accP[m][0] = fma2(aw, b3.x, accP[m][0]);                      \
                accP[m][1] = fma2(aw, b3.y, accP[m][1]);                      \
            }                                                                 \
        }                                                                     \
    }

// ---------------------------------------------------------------------------
// Kernel: gemmR — pre = x @ W1r + b1l  (side stream; overlaps CSR build)
// ---------------------------------------------------------------------------
__global__ __launch_bounds__(256) void gemmR_kernel(
    const float* __restrict__ x, const float* __restrict__ W1r,
    const float* __restrict__ b1l) {
    __shared__ float sB[64 * 64];
    int t  = threadIdx.x;
    int cg = t & 15;
    int ng = t >> 4;
    int nodeBase = blockIdx.x * 128 + ng * 8;

    unsigned long long accP[8][2];
#pragma unroll
    for (int m = 0; m < 8; m++) { accP[m][0] = 0ull; accP[m][1] = 0ull; }

#pragma unroll
    for (int i = 0; i < 4; i++) {
        int f4 = t + i * 256;
        ((float4*)sB)[f4] = ((const float4*)W1r)[f4];
    }
    __syncthreads();
    GEMM_CORE((const float4*)x, sB, accP, nodeBase, cg)
    float4 bias = ((const float4*)b1l)[cg];
#pragma unroll
    for (int m = 0; m < 8; m++) {
        int node = nodeBase + m;
        if (node < N_NODES) {
            float4 r;
            unpack2(accP[m][0], r.x, r.y);
            unpack2(accP[m][1], r.z, r.w);
            r.x += bias.x; r.y += bias.y; r.z += bias.z; r.w += bias.w;
            ((float4*)(g_pre + (size_t)node * 64))[cg] = r;
        }
    }
}

// ---------------------------------------------------------------------------
// Kernel: gemm12 — fused layer-1 + layer-2 node GEMMs (h kept in smem).
// ---------------------------------------------------------------------------
__global__ __launch_bounds__(256) void gemm12_kernel(
    const float* __restrict__ W1l,
    const float* __restrict__ W2l, const float* __restrict__ b2l,
    const float* __restrict__ W2r, float* __restrict__ out) {
    __shared__ float sB[64 * 64];     // 16 KB
    __shared__ float sH[128 * 64];    // 32 KB
    int t  = threadIdx.x;
    int cg = t & 15;
    int ng = t >> 4;
    int nodeBase = blockIdx.x * 128 + ng * 8;

    unsigned long long accP[8][2];
#pragma unroll
    for (int m = 0; m < 8; m++) { accP[m][0] = 0ull; accP[m][1] = 0ull; }

    // ---- pass 1: h = relu(sum1 @ W1l + pre) ----
#pragma unroll
    for (int i = 0; i < 4; i++) {
        int f4 = t + i * 256;
        ((float4*)sB)[f4] = ((const float4*)W1l)[f4];
    }
    __syncthreads();
    GEMM_CORE((const float4*)g_sum1, sB, accP, nodeBase, cg)
#pragma unroll
    for (int m = 0; m < 8; m++) {
        int cn = min(nodeBase + m, N_NODES - 1);
        float4 p = ((const float4*)(g_pre + (size_t)cn * 64))[cg];
        float4 r;
        unpack2(accP[m][0], r.x, r.y);
        unpack2(accP[m][1], r.z, r.w);
        r.x = fmaxf(r.x + p.x, 0.f);
        r.y = fmaxf(r.y + p.y, 0.f);
        r.z = fmaxf(r.z + p.z, 0.f);
        r.w = fmaxf(r.w + p.w, 0.f);
        ((float4*)(sH + (ng * 8 + m) * 64))[cg] = r;
    }
    __syncthreads();

    // ---- pass 2 ----
#pragma unroll
    for (int i = 0; i < 4; i++) {
        int f4 = t + i * 256;
        int k  = f4 >> 4;
        int jq = f4 & 15;
        float4 v = (jq < 8) ? ((const float4*)W2l)[k * 8 + jq]
                            : ((const float4*)W2r)[k * 8 + (jq - 8)];
        ((float4*)sB)[f4] = v;
    }
#pragma unroll
    for (int m = 0; m < 8; m++) { accP[m][0] = 0ull; accP[m][1] = 0ull; }
    __syncthreads();
    GEMM_CORE_L((const float4*)sH, sB, accP, ng * 8, cg)
#pragma unroll
    for (int m = 0; m < 8; m++) {
        int node = nodeBase + m;
        if (node < N_NODES) {
            float4 r;
            unpack2(accP[m][0], r.x, r.y);
            unpack2(accP[m][1], r.z, r.w);
            if (cg < 8) {
                __half2 h0 = __floats2half2_rn(r.x, r.y);
                __half2 h1 = __floats2half2_rn(r.z, r.w);
                uint2 packed = make_uint2(h2_bits(h0), h2_bits(h1));
                ((uint2*)(g_p2h + (size_t)node * 32))[cg] = packed;
            } else {
                float4 bias = ((const float4*)b2l)[cg - 8];
                r.x += bias.x; r.y += bias.y; r.z += bias.z; r.w += bias.w;
                ((float4*)(out + (size_t)node * 32))[cg - 8] = r;
            }
        }
    }
}

// ---------------------------------------------------------------------------
// Kernel: agg2 + final — one warp per node; 4 neighbors per round.
// fp16 tree-sum over each 4-neighbor group, then one fp32 accumulate.
// ---------------------------------------------------------------------------
__global__ __launch_bounds__(256) void agg2_kernel(float* __restrict__ out) {
    int warp = (blockIdx.x * blockDim.x + threadIdx.x) >> 5;
    if (warp >= N_NODES) return;
    unsigned lane = threadIdx.x & 31;
    unsigned g    = lane >> 3;
    unsigned l    = lane & 7;
    int row = g_rowstart[warp];
    int n   = g_rowstart[warp + 1] - row;
    const int* cs = g_csr + row;
    const uint2* p2 = (const uint2*)g_p2h;
    float4 acc = make_float4(0.f, 0.f, 0.f, 0.f);
    int k = 0;
    for (; k + 16 <= n; k += 16) {
        unsigned i0 = (unsigned)cs[k + 0  + g] * 8u + l;
        unsigned i1 = (unsigned)cs[k + 4  + g] * 8u + l;
        unsigned i2 = (unsigned)cs[k + 8  + g] * 8u + l;
        unsigned i3 = (unsigned)cs[k + 12 + g] * 8u + l;
        uint2 u0 = p2[i0];
        uint2 u1 = p2[i1];
        uint2 u2 = p2[i2];
        uint2 u3 = p2[i3];
        __half2 sx = __hadd2(__hadd2(u2h(u0.x), u2h(u1.x)),
                             __hadd2(u2h(u2.x), u2h(u3.x)));
        __half2 sy = __hadd2(__hadd2(u2h(u0.y), u2h(u1.y)),
                             __hadd2(u2h(u2.y), u2h(u3.y)));
        float2 fx = __half22float2(sx);
        float2 fy = __half22float2(sy);
        acc.x += fx.x; acc.y += fx.y; acc.z += fy.x; acc.w += fy.y;
    }
    for (; k < n; k += 4) {
        int e = k + g;
        uint2 u = make_uint2(0u, 0u);
        if (e < n) u = p2[(unsigned)cs[e] * 8u + l];
        float2 fx = u32_to_f2(u.x);
        float2 fy = u32_to_f2(u.y);
        acc.x += fx.x; acc.y += fx.y; acc.z += fy.x; acc.w += fy.y;
    }
#pragma unroll
    for (int off = 8; off <= 16; off <<= 1) {
        acc.x += __shfl_xor_sync(0xffffffffu, acc.x, off);
        acc.y += __shfl_xor_sync(0xffffffffu, acc.y, off);
        acc.z += __shfl_xor_sync(0xffffffffu, acc.z, off);
        acc.w += __shfl_xor_sync(0xffffffffu, acc.w, off);
    }
    if (lane < 8) {
        float invd = 1.0f / (float)max(n, 1);
        unsigned oi = (unsigned)warp * 8u + l;
        float4 o = ((float4*)out)[oi];
        o.x = fmaf(acc.x, invd, o.x);
        o.y = fmaf(acc.y, invd, o.y);
        o.z = fmaf(acc.z, invd, o.z);
        o.w = fmaf(acc.w, invd, o.w);
        ((float4*)out)[oi] = o;
    }
}

extern "C" void kernel_launch(void* const* d_in, const int* in_sizes, int n_in,
                              void* d_out, int out_size) {
    const float* x   = (const float*)d_in[0];
    const int*   ei  = (const int*)d_in[1];   // int32
    const float* W1l = (const float*)d_in[2];
    const float* b1l = (const float*)d_in[3];
    const float* W1r = (const float*)d_in[4];
    const float* W2l = (const float*)d_in[5];
    const float* b2l = (const float*)d_in[6];
    const float* W2r = (const float*)d_in[7];
    float* out = (float*)d_out;
    int E = in_sizes[1] / 2;

    static cudaStream_t s_side = nullptr;
    static cudaEvent_t  ev_fork = nullptr, ev_join = nullptr;
    if (s_side == nullptr) {
        cudaStreamCreateWithFlags(&s_side, cudaStreamNonBlocking);
        cudaEventCreateWithFlags(&ev_fork, cudaEventDisableTiming);
        cudaEventCreateWithFlags(&ev_join, cudaEventDisableTiming);
    }

    cudaEventRecord(ev_fork, 0);
    cudaStreamWaitEvent(s_side, ev_fork, 0);

    void *p_degi, *p_cnt;
    cudaGetSymbolAddress(&p_degi, g_degi);
    cudaGetSymbolAddress(&p_cnt,  g_scan_count);
    cudaMemsetAsync(p_degi, 0, (size_t)N_NODES * sizeof(int), 0);
    cudaMemsetAsync(p_cnt,  0, sizeof(int), 0);

    int gemmBlocks = (N_NODES + 127) / 128;

    {   // kernel 1: hist + rank + x->fp16
        int tE = (E + 3) / 4;
        int tX = (N_NODES * IN_C + 7) / 8;
        int threads = tE > tX ? tE : tX;
        hist_xconv_kernel<<<(threads + 255) / 256, 256>>>(ei, x, E);
    }
    scan_fused_kernel<<<SCAN_BLOCKS, 1024>>>();       // kernel 2
    {
        int threads = (E + 3) / 4;                    // kernel 3
        fill_kernel<<<(threads + 255) / 256, 256>>>(ei, E);
    }
    {   // kernel 4 (profiled): agg1
        unsigned total = (unsigned)N_NODES * 32u;
        agg1_kernel<<<(total + 255) / 256, 256>>>();
    }
    gemmR_kernel<<<gemmBlocks, 256, 0, s_side>>>(x, W1r, b1l);
    cudaEventRecord(ev_join, s_side);
    cudaStreamWaitEvent(0, ev_join, 0);

    gemm12_kernel<<<gemmBlocks, 256>>>(W1l, W2l, b2l, W2r, out);
    {   // agg2 + final add
        unsigned total = (unsigned)N_NODES * 32u;
        agg2_kernel<<<(total + 255) / 256, 256>>>(out);
    }
}